// round 2
// baseline (speedup 1.0000x reference)
#include <cuda_runtime.h>
#include <mma.h>
#include <math.h>
#include <stdint.h>
#include <stddef.h>

using namespace nvcuda;

// ---------------------------------------------------------------------------
// TWSABlock round 2: GEMMs on tensor cores via 3xTF32 (hi/lo split) wmma.
// BN folded into conv weights, LN folded into GEMM B-operand.
// ---------------------------------------------------------------------------

#define HW 4096
#define NB 16
#define CC 256
#define EPS 1e-5f

// ------------------------------- scratch ----------------------------------
__device__ float g_t1 [NB * CC * HW];
__device__ float g_t2 [NB * CC * HW];
__device__ float g_x1 [NB * CC * HW];
__device__ float g_ob [NB * CC * HW];
__device__ float g_x2 [NB * CC * HW];
__device__ float g_qkv[NB * 3 * CC * HW];
__device__ float g_hid[NB * 4 * CC * HW];
__device__ float g_mu [NB * HW];
__device__ float g_rs [NB * HW];
__device__ float g_w1f [CC * CC];
__device__ float g_b1f [CC];
__device__ float g_dwf [CC * 9];
__device__ float g_dbf [CC];
__device__ float g_qkvf [3 * CC * CC];
__device__ float g_qkvbf[3 * CC];
__device__ float g_m1f [4 * CC * CC];
__device__ float g_m1bf[4 * CC];

// ------------------------------ prep kernel -------------------------------
__global__ void __launch_bounds__(256) prep_kernel(
    const float* __restrict__ conv1_w, const float* __restrict__ conv1_b,
    const float* __restrict__ bn1_g,  const float* __restrict__ bn1_b,
    const float* __restrict__ bn1_m,  const float* __restrict__ bn1_v,
    const float* __restrict__ dw_w,   const float* __restrict__ dw_b,
    const float* __restrict__ bn2_g,  const float* __restrict__ bn2_b,
    const float* __restrict__ bn2_m,  const float* __restrict__ bn2_v,
    const float* __restrict__ qkv_w,  const float* __restrict__ qkv_b,
    const float* __restrict__ ln1_g,  const float* __restrict__ ln1_b,
    const float* __restrict__ mlp_w1, const float* __restrict__ mlp_b1,
    const float* __restrict__ ln2_g,  const float* __restrict__ ln2_b)
{
    __shared__ float red[8];
    const int r = blockIdx.x;
    const int tid = threadIdx.x;

    if (r < 256) {
        float inv1 = bn1_g[r] * rsqrtf(bn1_v[r] + EPS);
        g_w1f[r * 256 + tid] = conv1_w[r * 256 + tid] * inv1;
        if (tid == 0) g_b1f[r] = conv1_b[r] * inv1 + bn1_b[r] - bn1_m[r] * inv1;
        float inv2 = bn2_g[r] * rsqrtf(bn2_v[r] + EPS);
        if (tid < 9) g_dwf[r * 9 + tid] = dw_w[r * 9 + tid] * inv2;
        if (tid == 0) g_dbf[r] = dw_b[r] * inv2 + bn2_b[r] - bn2_m[r] * inv2;
    }
    if (r < 768) {
        float w = qkv_w[r * 256 + tid];
        g_qkvf[r * 256 + tid] = w * ln1_g[tid];
        float part = w * ln1_b[tid];
        #pragma unroll
        for (int o = 16; o; o >>= 1) part += __shfl_xor_sync(0xffffffffu, part, o);
        if ((tid & 31) == 0) red[tid >> 5] = part;
        __syncthreads();
        if (tid == 0) {
            float s = 0.f;
            #pragma unroll
            for (int w2 = 0; w2 < 8; w2++) s += red[w2];
            g_qkvbf[r] = qkv_b[r] + s;
        }
        __syncthreads();
    }
    if (r < 1024) {
        float w = mlp_w1[r * 256 + tid];
        g_m1f[r * 256 + tid] = w * ln2_g[tid];
        float part = w * ln2_b[tid];
        #pragma unroll
        for (int o = 16; o; o >>= 1) part += __shfl_xor_sync(0xffffffffu, part, o);
        if ((tid & 31) == 0) red[tid >> 5] = part;
        __syncthreads();
        if (tid == 0) {
            float s = 0.f;
            #pragma unroll
            for (int w2 = 0; w2 < 8; w2++) s += red[w2];
            g_m1bf[r] = mlp_b1[r] + s;
        }
    }
}

// ------------------------- tf32 tensor-core GEMM ---------------------------
// out[b, oc, p] = epilog( sum_c A[oc,c] * Bop(b,c,p) + bias[oc] )
// 3xTF32: x = hi + lo (both tf32);  D += hi*hi + hi*lo + lo*hi.
// Block tile 128x128x16, 8 warps of 32x64, wmma m16n16k8.

__device__ __forceinline__ float tf32_rna(float x) {
    unsigned r;
    asm("cvt.rna.tf32.f32 %0, %1;" : "=r"(r) : "f"(x));
    return __uint_as_float(r);
}

constexpr int BM = 128, BN = 128, BK = 16;
constexpr int LDA = 24;    // BK + pad, keeps 32B alignment per row
constexpr int LDB = 136;   // BN + pad
constexpr int LDC = 136;
constexpr int A_BUF = BM * LDA;    // 3072 floats
constexpr int B_BUF = BK * LDB;    // 2176 floats
constexpr int OFF_AHI = 0;
constexpr int OFF_ALO = 2 * A_BUF;
constexpr int OFF_BHI = 4 * A_BUF;
constexpr int OFF_BLO = 4 * A_BUF + 2 * B_BUF;
constexpr int SMEM_FLOATS = 4 * A_BUF + 4 * B_BUF;   // 20992
constexpr int SMEM_BYTES = SMEM_FLOATS * 4;          // 83968

template<int KD, bool LN, int EP>
__global__ void __launch_bounds__(256) tgemm_kernel(
    const float* __restrict__ A, const float* __restrict__ B,
    const float* __restrict__ bias,
    const float* __restrict__ mu, const float* __restrict__ rstd,
    const float* __restrict__ res, float* __restrict__ out, int Cout)
{
    extern __shared__ __align__(16) float sm[];
    float* As_hi = sm + OFF_AHI;
    float* As_lo = sm + OFF_ALO;
    float* Bs_hi = sm + OFF_BHI;
    float* Bs_lo = sm + OFF_BLO;
    float* Cs    = sm;   // epilogue aliases pipeline buffers

    const int b   = blockIdx.z;
    const int ocb = blockIdx.y * BM;
    const int pb  = blockIdx.x * BN;
    const int tid = threadIdx.x;
    const int wid = tid >> 5;
    const int wm  = wid >> 1;    // 0..3 (M)
    const int wn  = wid & 1;     // 0..1 (N)

    // global loaders: A rows {ar, ar+64} x 4 cols; B rows {br, br+8} x 4 cols
    const int ar = tid >> 2, aq = (tid & 3) * 4;
    const int br = tid >> 5, bq = (tid & 31) * 4;
    const float* Ag = A + (size_t)(ocb + ar) * KD + aq;
    const float* Bg = B + (size_t)b * KD * HW + (size_t)br * HW + pb + bq;

    float4 mu4 = {0, 0, 0, 0}, rs4 = {1, 1, 1, 1};
    if (LN) {
        const int g = (b << 12) + pb + bq;
        mu4 = *reinterpret_cast<const float4*>(&mu[g]);
        rs4 = *reinterpret_cast<const float4*>(&rstd[g]);
    }

    wmma::fragment<wmma::accumulator, 16, 16, 8, float> acc[2][4];
    #pragma unroll
    for (int i = 0; i < 2; i++)
        #pragma unroll
        for (int j = 0; j < 4; j++) wmma::fill_fragment(acc[i][j], 0.f);

    float4 av0, av1, bv0, bv1;

    auto loadG = [&](int k0) {
        av0 = *reinterpret_cast<const float4*>(Ag + k0);
        av1 = *reinterpret_cast<const float4*>(Ag + (size_t)64 * KD + k0);
        bv0 = *reinterpret_cast<const float4*>(Bg + (size_t)k0 * HW);
        bv1 = *reinterpret_cast<const float4*>(Bg + (size_t)(k0 + 8) * HW);
        if (LN) {
            bv0.x = (bv0.x - mu4.x) * rs4.x; bv0.y = (bv0.y - mu4.y) * rs4.y;
            bv0.z = (bv0.z - mu4.z) * rs4.z; bv0.w = (bv0.w - mu4.w) * rs4.w;
            bv1.x = (bv1.x - mu4.x) * rs4.x; bv1.y = (bv1.y - mu4.y) * rs4.y;
            bv1.z = (bv1.z - mu4.z) * rs4.z; bv1.w = (bv1.w - mu4.w) * rs4.w;
        }
    };

    auto split4 = [](float4 v, float4& hi, float4& lo) {
        hi.x = tf32_rna(v.x); lo.x = tf32_rna(v.x - hi.x);
        hi.y = tf32_rna(v.y); lo.y = tf32_rna(v.y - hi.y);
        hi.z = tf32_rna(v.z); lo.z = tf32_rna(v.z - hi.z);
        hi.w = tf32_rna(v.w); lo.w = tf32_rna(v.w - hi.w);
    };

    auto storeS = [&](int buf) {
        float4 hi, lo;
        float* ah = As_hi + buf * A_BUF;
        float* al = As_lo + buf * A_BUF;
        float* bh = Bs_hi + buf * B_BUF;
        float* bl = Bs_lo + buf * B_BUF;
        split4(av0, hi, lo);
        *reinterpret_cast<float4*>(&ah[ar * LDA + aq]) = hi;
        *reinterpret_cast<float4*>(&al[ar * LDA + aq]) = lo;
        split4(av1, hi, lo);
        *reinterpret_cast<float4*>(&ah[(ar + 64) * LDA + aq]) = hi;
        *reinterpret_cast<float4*>(&al[(ar + 64) * LDA + aq]) = lo;
        split4(bv0, hi, lo);
        *reinterpret_cast<float4*>(&bh[br * LDB + bq]) = hi;
        *reinterpret_cast<float4*>(&bl[br * LDB + bq]) = lo;
        split4(bv1, hi, lo);
        *reinterpret_cast<float4*>(&bh[(br + 8) * LDB + bq]) = hi;
        *reinterpret_cast<float4*>(&bl[(br + 8) * LDB + bq]) = lo;
    };

    auto compute = [&](int buf) {
        const float* ah = As_hi + buf * A_BUF;
        const float* al = As_lo + buf * A_BUF;
        const float* bh = Bs_hi + buf * B_BUF;
        const float* bl = Bs_lo + buf * B_BUF;
        #pragma unroll
        for (int ks = 0; ks < 2; ks++) {
            wmma::fragment<wmma::matrix_a, 16, 16, 8, wmma::precision::tf32,
                           wmma::row_major> fa_hi[2], fa_lo[2];
            wmma::fragment<wmma::matrix_b, 16, 16, 8, wmma::precision::tf32,
                           wmma::row_major> fb_hi[4], fb_lo[4];
            #pragma unroll
            for (int i = 0; i < 2; i++) {
                const int ro = (wm * 32 + i * 16) * LDA + ks * 8;
                wmma::load_matrix_sync(fa_hi[i], ah + ro, LDA);
                wmma::load_matrix_sync(fa_lo[i], al + ro, LDA);
            }
            #pragma unroll
            for (int j = 0; j < 4; j++) {
                const int co = (ks * 8) * LDB + wn * 64 + j * 16;
                wmma::load_matrix_sync(fb_hi[j], bh + co, LDB);
                wmma::load_matrix_sync(fb_lo[j], bl + co, LDB);
            }
            #pragma unroll
            for (int i = 0; i < 2; i++)
                #pragma unroll
                for (int j = 0; j < 4; j++) {
                    wmma::mma_sync(acc[i][j], fa_hi[i], fb_hi[j], acc[i][j]);
                    wmma::mma_sync(acc[i][j], fa_hi[i], fb_lo[j], acc[i][j]);
                    wmma::mma_sync(acc[i][j], fa_lo[i], fb_hi[j], acc[i][j]);
                }
        }
    };

    // ------------------------ pipelined mainloop --------------------------
    const int NT = KD / BK;
    loadG(0);
    storeS(0);
    __syncthreads();
    for (int kt = 0; kt < NT; kt++) {
        const int cur = kt & 1;
        if (kt + 1 < NT) loadG((kt + 1) * BK);
        compute(cur);
        if (kt + 1 < NT) storeS(cur ^ 1);
        __syncthreads();
    }

    // ------------------------------ epilogue ------------------------------
    #pragma unroll
    for (int i = 0; i < 2; i++)
        #pragma unroll
        for (int j = 0; j < 4; j++)
            wmma::store_matrix_sync(
                Cs + (wm * 32 + i * 16) * LDC + wn * 64 + j * 16,
                acc[i][j], LDC, wmma::mem_row_major);
    __syncthreads();

    #pragma unroll
    for (int u = 0; u < 16; u++) {
        const int e = tid + u * 256;           // 0..4095 float4 slots
        const int row = e >> 5;                // 0..127
        const int q4  = (e & 31) * 4;          // col
        float4 v = *reinterpret_cast<const float4*>(&Cs[row * LDC + q4]);
        const int oc = ocb + row;
        const float bs = bias[oc];
        v.x += bs; v.y += bs; v.z += bs; v.w += bs;
        const size_t ob = ((size_t)b * Cout + oc) * HW + pb + q4;
        if (EP == 2) {
            v.x = v.x * normcdff(v.x);
            v.y = v.y * normcdff(v.y);
            v.z = v.z * normcdff(v.z);
            v.w = v.w * normcdff(v.w);
        }
        if (EP == 1) {
            const float4 r = *reinterpret_cast<const float4*>(&res[ob]);
            v.x += r.x; v.y += r.y; v.z += r.z; v.w += r.w;
        }
        *reinterpret_cast<float4*>(&out[ob]) = v;
    }
}

// ------------------------------ dw conv 3x3 --------------------------------
__global__ void __launch_bounds__(256) dwconv_kernel(
    const float* __restrict__ in, float* __restrict__ out)
{
    const int plane = blockIdx.x;
    const int c = plane & 255;
    const float* ip = in + (size_t)plane * HW;
    float* op = out + (size_t)plane * HW;
    float w[9];
    #pragma unroll
    for (int k = 0; k < 9; k++) w[k] = g_dwf[c * 9 + k];
    const float bias = g_dbf[c];

    for (int idx = threadIdx.x; idx < HW; idx += 256) {
        const int y = idx >> 6, x = idx & 63;
        float acc = bias;
        #pragma unroll
        for (int ky = 0; ky < 3; ky++) {
            const int yy = y + ky - 1;
            if (yy < 0 || yy > 63) continue;
            #pragma unroll
            for (int kx = 0; kx < 3; kx++) {
                const int xx = x + kx - 1;
                if (xx < 0 || xx > 63) continue;
                acc = fmaf(w[ky * 3 + kx], ip[yy * 64 + xx], acc);
            }
        }
        op[idx] = acc;
    }
}

// ------------------------------- LN stats ----------------------------------
__global__ void __launch_bounds__(256) lnstats_kernel(
    const float* __restrict__ x, float* __restrict__ mu, float* __restrict__ rs)
{
    const int g = blockIdx.x * 256 + threadIdx.x;
    const int b = g >> 12, p = g & 4095;
    const float* base = x + (size_t)b * CC * HW + p;
    float s = 0.f, s2 = 0.f;
    #pragma unroll 8
    for (int c = 0; c < CC; c++) {
        const float v = base[(size_t)c * HW];
        s += v;
        s2 = fmaf(v, v, s2);
    }
    const float m = s * (1.f / CC);
    const float var = s2 * (1.f / CC) - m * m;
    mu[g] = m;
    rs[g] = rsqrtf(var + EPS);
}

// ---------------------------- window attention ------------------------------
__global__ void __launch_bounds__(256) attn_kernel(
    const float* __restrict__ qkv, float* __restrict__ o)
{
    __shared__ __align__(16) float bufA[64 * 68];
    __shared__ __align__(16) float bufB[64 * 68];

    const int bx = blockIdx.x;
    const int head = bx & 3;
    const int win  = bx >> 2;
    const int b    = win >> 6;
    const int wrem = win & 63;
    const int pbase = (wrem >> 3) * 512 + (wrem & 7) * 8;

    const float* qb = qkv + ((size_t)b * 768 + head * 64) * HW;
    const float* kb = qb + (size_t)256 * HW;
    const float* vb = qb + (size_t)512 * HW;

    const int tid = threadIdx.x;
    const int tx = tid & 15, ty = tid >> 4;
    const int ty4 = ty << 2, tx4 = tx << 2;

    for (int idx = tid; idx < 4096; idx += 256) {
        const int d = idx >> 6, t = idx & 63;
        const int p = pbase + (t >> 3) * 64 + (t & 7);
        bufA[d * 64 + t] = qb[(size_t)d * HW + p];
        bufB[d * 64 + t] = kb[(size_t)d * HW + p];
    }
    __syncthreads();

    float s[4][4];
    #pragma unroll
    for (int i = 0; i < 4; i++)
        #pragma unroll
        for (int j = 0; j < 4; j++) s[i][j] = 0.f;

    for (int d = 0; d < 64; d++) {
        const float4 q4 = *reinterpret_cast<const float4*>(&bufA[d * 64 + ty4]);
        const float4 k4 = *reinterpret_cast<const float4*>(&bufB[d * 64 + tx4]);
        float q[4] = {q4.x, q4.y, q4.z, q4.w};
        float k[4] = {k4.x, k4.y, k4.z, k4.w};
        #pragma unroll
        for (int i = 0; i < 4; i++)
            #pragma unroll
            for (int j = 0; j < 4; j++)
                s[i][j] = fmaf(q[i], k[j], s[i][j]);
    }

    const float scale = 0.125f;
    #pragma unroll
    for (int i = 0; i < 4; i++) {
        float mx = -1e30f;
        #pragma unroll
        for (int j = 0; j < 4; j++) { s[i][j] *= scale; mx = fmaxf(mx, s[i][j]); }
        #pragma unroll
        for (int off = 1; off < 16; off <<= 1)
            mx = fmaxf(mx, __shfl_xor_sync(0xffffffffu, mx, off));
        float sum = 0.f;
        #pragma unroll
        for (int j = 0; j < 4; j++) { s[i][j] = __expf(s[i][j] - mx); sum += s[i][j]; }
        #pragma unroll
        for (int off = 1; off < 16; off <<= 1)
            sum += __shfl_xor_sync(0xffffffffu, sum, off);
        const float inv = 1.f / sum;
        #pragma unroll
        for (int j = 0; j < 4; j++) s[i][j] *= inv;
    }
    __syncthreads();

    #pragma unroll
    for (int i = 0; i < 4; i++)
        #pragma unroll
        for (int j = 0; j < 4; j++)
            bufA[(ty4 + i) * 68 + tx4 + j] = s[i][j];
    for (int idx = tid; idx < 4096; idx += 256) {
        const int d = idx >> 6, m = idx & 63;
        const int p = pbase + (m >> 3) * 64 + (m & 7);
        bufB[m * 68 + d] = vb[(size_t)d * HW + p];
    }
    __syncthreads();

    float oacc[4][4];
    #pragma unroll
    for (int i = 0; i < 4; i++)
        #pragma unroll
        for (int j = 0; j < 4; j++) oacc[i][j] = 0.f;

    for (int m = 0; m < 64; m++) {
        float p4[4];
        #pragma unroll
        for (int i = 0; i < 4; i++) p4[i] = bufA[(ty4 + i) * 68 + m];
        const float4 v4 = *reinterpret_cast<const float4*>(&bufB[m * 68 + tx4]);
        float v[4] = {v4.x, v4.y, v4.z, v4.w};
        #pragma unroll
        for (int i = 0; i < 4; i++)
            #pragma unroll
            for (int j = 0; j < 4; j++)
                oacc[i][j] = fmaf(p4[i], v[j], oacc[i][j]);
    }
    __syncthreads();

    #pragma unroll
    for (int i = 0; i < 4; i++)
        #pragma unroll
        for (int j = 0; j < 4; j++)
            bufA[(tx4 + j) * 68 + ty4 + i] = oacc[i][j];
    __syncthreads();

    float* ob = o + ((size_t)b * 256 + head * 64) * HW;
    for (int idx = tid; idx < 4096; idx += 256) {
        const int d = idx >> 6, t = idx & 63;
        const int p = pbase + (t >> 3) * 64 + (t & 7);
        ob[(size_t)d * HW + p] = bufA[d * 68 + t];
    }
}

// ------------------------------- launcher ----------------------------------
extern "C" void kernel_launch(void* const* d_in, const int* in_sizes, int n_in,
                              void* d_out, int out_size)
{
    (void)in_sizes; (void)n_in; (void)out_size;
    const float* x       = (const float*)d_in[0];
    const float* conv1_w = (const float*)d_in[1];
    const float* conv1_b = (const float*)d_in[2];
    const float* bn1_g   = (const float*)d_in[3];
    const float* bn1_b   = (const float*)d_in[4];
    const float* bn1_m   = (const float*)d_in[5];
    const float* bn1_v   = (const float*)d_in[6];
    const float* dw_w    = (const float*)d_in[7];
    const float* dw_b    = (const float*)d_in[8];
    const float* bn2_g   = (const float*)d_in[9];
    const float* bn2_b   = (const float*)d_in[10];
    const float* bn2_m   = (const float*)d_in[11];
    const float* bn2_v   = (const float*)d_in[12];
    const float* conv3_w = (const float*)d_in[13];
    const float* conv3_b = (const float*)d_in[14];
    const float* ln1_g   = (const float*)d_in[15];
    const float* ln1_b   = (const float*)d_in[16];
    const float* qkv_w   = (const float*)d_in[17];
    const float* qkv_b   = (const float*)d_in[18];
    const float* proj_w  = (const float*)d_in[19];
    const float* proj_b  = (const float*)d_in[20];
    const float* ln2_g   = (const float*)d_in[21];
    const float* ln2_b   = (const float*)d_in[22];
    const float* mlp_w1  = (const float*)d_in[23];
    const float* mlp_b1  = (const float*)d_in[24];
    const float* mlp_w2  = (const float*)d_in[25];
    const float* mlp_b2  = (const float*)d_in[26];
    float* out = (float*)d_out;

    float *t1, *t2, *x1, *ob, *x2, *qkvb, *hid, *mu, *rs;
    float *w1f, *b1f, *qkvf, *qkvbf, *m1f, *m1bf;
    cudaGetSymbolAddress((void**)&t1,    g_t1);
    cudaGetSymbolAddress((void**)&t2,    g_t2);
    cudaGetSymbolAddress((void**)&x1,    g_x1);
    cudaGetSymbolAddress((void**)&ob,    g_ob);
    cudaGetSymbolAddress((void**)&x2,    g_x2);
    cudaGetSymbolAddress((void**)&qkvb,  g_qkv);
    cudaGetSymbolAddress((void**)&hid,   g_hid);
    cudaGetSymbolAddress((void**)&mu,    g_mu);
    cudaGetSymbolAddress((void**)&rs,    g_rs);
    cudaGetSymbolAddress((void**)&w1f,   g_w1f);
    cudaGetSymbolAddress((void**)&b1f,   g_b1f);
    cudaGetSymbolAddress((void**)&qkvf,  g_qkvf);
    cudaGetSymbolAddress((void**)&qkvbf, g_qkvbf);
    cudaGetSymbolAddress((void**)&m1f,   g_m1f);
    cudaGetSymbolAddress((void**)&m1bf,  g_m1bf);

    // raise dynamic smem limits (idempotent, not a stream op)
    cudaFuncSetAttribute(tgemm_kernel<256,  false, 0>,
                         cudaFuncAttributeMaxDynamicSharedMemorySize, SMEM_BYTES);
    cudaFuncSetAttribute(tgemm_kernel<256,  false, 1>,
                         cudaFuncAttributeMaxDynamicSharedMemorySize, SMEM_BYTES);
    cudaFuncSetAttribute(tgemm_kernel<256,  true,  0>,
                         cudaFuncAttributeMaxDynamicSharedMemorySize, SMEM_BYTES);
    cudaFuncSetAttribute(tgemm_kernel<256,  true,  2>,
                         cudaFuncAttributeMaxDynamicSharedMemorySize, SMEM_BYTES);
    cudaFuncSetAttribute(tgemm_kernel<1024, false, 1>,
                         cudaFuncAttributeMaxDynamicSharedMemorySize, SMEM_BYTES);

    // 0) fold BN/LN into weights
    prep_kernel<<<1024, 256>>>(conv1_w, conv1_b, bn1_g, bn1_b, bn1_m, bn1_v,
                               dw_w, dw_b, bn2_g, bn2_b, bn2_m, bn2_v,
                               qkv_w, qkv_b, ln1_g, ln1_b,
                               mlp_w1, mlp_b1, ln2_g, ln2_b);

    const dim3 gConv(32, 2, 16);    // Cout=256
    const dim3 gQkv (32, 6, 16);    // Cout=768
    const dim3 gMlp1(32, 8, 16);    // Cout=1024

    // 1) conv1 + BN1 (folded)
    tgemm_kernel<256, false, 0><<<gConv, 256, SMEM_BYTES>>>(
        w1f, x, b1f, nullptr, nullptr, nullptr, t1, 256);
    // 2) dw 3x3 + BN2 (folded)
    dwconv_kernel<<<NB * CC, 256>>>(t1, t2);
    // 3) conv3 + residual(x)
    tgemm_kernel<256, false, 1><<<gConv, 256, SMEM_BYTES>>>(
        conv3_w, t2, conv3_b, nullptr, nullptr, x, x1, 256);
    // 4) LN1 stats
    lnstats_kernel<<<256, 256>>>(x1, mu, rs);
    // 5) QKV gemm (LN fused)
    tgemm_kernel<256, true, 0><<<gQkv, 256, SMEM_BYTES>>>(
        qkvf, x1, qkvbf, mu, rs, nullptr, qkvb, 768);
    // 6) window attention
    attn_kernel<<<4096, 256>>>(qkvb, ob);
    // 7) proj + residual(x1)
    tgemm_kernel<256, false, 1><<<gConv, 256, SMEM_BYTES>>>(
        proj_w, ob, proj_b, nullptr, nullptr, x1, x2, 256);
    // 8) LN2 stats
    lnstats_kernel<<<256, 256>>>(x2, mu, rs);
    // 9) MLP1 (LN fused) + GELU
    tgemm_kernel<256, true, 2><<<gMlp1, 256, SMEM_BYTES>>>(
        m1f, x2, m1bf, mu, rs, nullptr, hid, 1024);
    // 10) MLP2 + residual(x2) -> out
    tgemm_kernel<1024, false, 1><<<gConv, 256, SMEM_BYTES>>>(
        mlp_w2, hid, mlp_b2, nullptr, nullptr, x2, out, 256);
}

// round 4
// speedup vs baseline: 3.0171x; 3.0171x over previous
#include <cuda_runtime.h>
#include <cuda_fp16.h>
#include <math.h>
#include <stdint.h>
#include <stddef.h>

// ---------------------------------------------------------------------------
// TWSABlock round 4: token-major pipeline, GEMMs via mma.sync.m16n8k16.f16
// with fp16 hi/lo 3-pass split (fp32-grade accuracy). cp.async 2-stage.
// (tcgen05 unavailable: harness ptxas target is plain sm_100.)
// ---------------------------------------------------------------------------

#define HW 4096
#define NB 16
#define CC 256
#define NTOK (NB * HW)          // 65536 tokens
#define EPS 1e-5f

// ============================ small helpers ================================
__device__ __forceinline__ uint32_t smem_u32(const void* p) {
    uint32_t a;
    asm("{ .reg .u64 t; cvta.to.shared.u64 t, %1; cvt.u32.u64 %0, t; }"
        : "=r"(a) : "l"(p));
    return a;
}
__device__ __forceinline__ void hsplit(float v, __half& h, __half& l) {
    h = __float2half_rn(v);
    l = __float2half_rn(v - __half2float(h));
}
__device__ __forceinline__ void ldsm4(uint32_t addr, uint32_t* r) {
    asm volatile("ldmatrix.sync.aligned.m8n8.x4.shared.b16 {%0,%1,%2,%3}, [%4];"
                 : "=r"(r[0]), "=r"(r[1]), "=r"(r[2]), "=r"(r[3]) : "r"(addr));
}
__device__ __forceinline__ void mma16816(float* c, const uint32_t* a,
                                         uint32_t b0, uint32_t b1) {
    asm volatile(
        "mma.sync.aligned.m16n8k16.row.col.f32.f16.f16.f32 "
        "{%0,%1,%2,%3}, {%4,%5,%6,%7}, {%8,%9}, {%0,%1,%2,%3};"
        : "+f"(c[0]), "+f"(c[1]), "+f"(c[2]), "+f"(c[3])
        : "r"(a[0]), "r"(a[1]), "r"(a[2]), "r"(a[3]), "r"(b0), "r"(b1));
}
#define CP_ASYNC16(dst, src) \
    asm volatile("cp.async.cg.shared.global [%0], [%1], 16;" :: "r"(dst), "l"(src))
#define CP_COMMIT() asm volatile("cp.async.commit_group;" ::: "memory")

// ============================== scratch ====================================
// fp32 token-major activations
__device__ float g_xT [NTOK * CC];
__device__ float g_t1 [NTOK * CC];
__device__ float g_x1 [NTOK * CC];
__device__ float g_x2 [NTOK * CC];
__device__ float g_qkv[NTOK * 3 * CC];
__device__ float g_y  [NTOK * CC];
// fp16 hi/lo GEMM inputs, token-major [p][c]
__device__ __half g_xh  [NTOK * CC], g_xl  [NTOK * CC];
__device__ __half g_t2h [NTOK * CC], g_t2l [NTOK * CC];
__device__ __half g_x1nh[NTOK * CC], g_x1nl[NTOK * CC];
__device__ __half g_obh [NTOK * CC], g_obl [NTOK * CC];
__device__ __half g_x2nh[NTOK * CC], g_x2nl[NTOK * CC];
__device__ __half g_hidh[NTOK * 4 * CC], g_hidl[NTOK * 4 * CC];
// folded + split weights [oc][k]
__device__ __half g_w1h[CC * CC],     g_w1l[CC * CC];
__device__ __half g_w3h[CC * CC],     g_w3l[CC * CC];
__device__ __half g_wph[CC * CC],     g_wpl[CC * CC];
__device__ __half g_wqh[3 * CC * CC], g_wql[3 * CC * CC];
__device__ __half g_m1h[4 * CC * CC], g_m1l[4 * CC * CC];
__device__ __half g_w2h[CC * 4 * CC], g_w2l[CC * 4 * CC];
// biases / dw weights fp32
__device__ float g_b1f[CC];
__device__ float g_dwf[CC * 9];
__device__ float g_dbf[CC];
__device__ float g_qkvbf[3 * CC];
__device__ float g_m1bf[4 * CC];

// ============================= prep kernel =================================
__global__ void __launch_bounds__(256) prep_kernel(
    const float* __restrict__ conv1_w, const float* __restrict__ conv1_b,
    const float* __restrict__ bn1_g,  const float* __restrict__ bn1_b,
    const float* __restrict__ bn1_m,  const float* __restrict__ bn1_v,
    const float* __restrict__ dw_w,   const float* __restrict__ dw_b,
    const float* __restrict__ bn2_g,  const float* __restrict__ bn2_b,
    const float* __restrict__ bn2_m,  const float* __restrict__ bn2_v,
    const float* __restrict__ conv3_w,
    const float* __restrict__ proj_w,
    const float* __restrict__ mlp_w2,
    const float* __restrict__ qkv_w,  const float* __restrict__ qkv_b,
    const float* __restrict__ ln1_g,  const float* __restrict__ ln1_b,
    const float* __restrict__ mlp_w1, const float* __restrict__ mlp_b1,
    const float* __restrict__ ln2_g,  const float* __restrict__ ln2_b)
{
    __shared__ float red[8];
    const int r = blockIdx.x;
    const int tid = threadIdx.x;
    __half h, l;

    if (r < 256) {
        float inv1 = bn1_g[r] * rsqrtf(bn1_v[r] + EPS);
        hsplit(conv1_w[r * 256 + tid] * inv1, h, l);
        g_w1h[r * 256 + tid] = h; g_w1l[r * 256 + tid] = l;
        hsplit(conv3_w[r * 256 + tid], h, l);
        g_w3h[r * 256 + tid] = h; g_w3l[r * 256 + tid] = l;
        hsplit(proj_w[r * 256 + tid], h, l);
        g_wph[r * 256 + tid] = h; g_wpl[r * 256 + tid] = l;
        #pragma unroll
        for (int k = 0; k < 4; k++) {
            hsplit(mlp_w2[r * 1024 + tid + 256 * k], h, l);
            g_w2h[r * 1024 + tid + 256 * k] = h;
            g_w2l[r * 1024 + tid + 256 * k] = l;
        }
        if (tid == 0) g_b1f[r] = conv1_b[r] * inv1 + bn1_b[r] - bn1_m[r] * inv1;
        float inv2 = bn2_g[r] * rsqrtf(bn2_v[r] + EPS);
        if (tid < 9) g_dwf[r * 9 + tid] = dw_w[r * 9 + tid] * inv2;
        if (tid == 0) g_dbf[r] = dw_b[r] * inv2 + bn2_b[r] - bn2_m[r] * inv2;
    }
    if (r < 768) {
        float w = qkv_w[r * 256 + tid];
        hsplit(w * ln1_g[tid], h, l);
        g_wqh[r * 256 + tid] = h; g_wql[r * 256 + tid] = l;
        float part = w * ln1_b[tid];
        #pragma unroll
        for (int o = 16; o; o >>= 1) part += __shfl_xor_sync(0xffffffffu, part, o);
        if ((tid & 31) == 0) red[tid >> 5] = part;
        __syncthreads();
        if (tid == 0) {
            float s = 0.f;
            #pragma unroll
            for (int w2 = 0; w2 < 8; w2++) s += red[w2];
            g_qkvbf[r] = qkv_b[r] + s;
        }
        __syncthreads();
    }
    if (r < 1024) {
        float w = mlp_w1[r * 256 + tid];
        hsplit(w * ln2_g[tid], h, l);
        g_m1h[r * 256 + tid] = h; g_m1l[r * 256 + tid] = l;
        float part = w * ln2_b[tid];
        #pragma unroll
        for (int o = 16; o; o >>= 1) part += __shfl_xor_sync(0xffffffffu, part, o);
        if ((tid & 31) == 0) red[tid >> 5] = part;
        __syncthreads();
        if (tid == 0) {
            float s = 0.f;
            #pragma unroll
            for (int w2 = 0; w2 < 8; w2++) s += red[w2];
            g_m1bf[r] = mlp_b1[r] + s;
        }
    }
}

// ======================= fp16 hi/lo mma.sync GEMM ==========================
// C[m=token][n=oc] = sum_k A[m][k] * W[n][k]  (both K-major, row.col mma)
// Block tile 128x128, BK=32, 8 warps (4m x 2n), warp tile 32x64.
// 3 passes: Ah*Wh + Ah*Wl + Al*Wh.
constexpr int ROWB  = 80;                 // smem row stride bytes (32 halves + pad)
constexpr int PLANE = 128 * ROWB;         // 10240 B
constexpr int STAGE = 4 * PLANE;          // 40960 B  (Ah, Al, Wh, Wl)
constexpr int GEMM_SMEM = 2 * STAGE;      // 81920 B

// EP: 0 bias -> fp32 ; 1 bias+res -> fp32 ; 2 gelu(bias) -> fp16 hi/lo
template<int K, int EP>
__global__ void __launch_bounds__(256, 1) hgemm(
    const __half* __restrict__ Ah, const __half* __restrict__ Al,
    const __half* __restrict__ Wh, const __half* __restrict__ Wl,
    const float* __restrict__ bias, const float* __restrict__ res,
    float* __restrict__ outf,
    __half* __restrict__ oh, __half* __restrict__ ol, int N)
{
    extern __shared__ __align__(128) char smem[];
    const uint32_t sb = smem_u32(smem);
    const int n0  = blockIdx.x * 128;
    const int m0  = blockIdx.y * 128;
    const int tid = threadIdx.x;
    const int lane = tid & 31, wid = tid >> 5;
    const int wm = wid >> 1, wn = wid & 1;

    const char* srcs[4] = {
        (const char*)(Ah + (size_t)m0 * K),
        (const char*)(Al + (size_t)m0 * K),
        (const char*)(Wh + (size_t)n0 * K),
        (const char*)(Wl + (size_t)n0 * K)};

    float c[2][8][4];
    #pragma unroll
    for (int i = 0; i < 2; i++)
        #pragma unroll
        for (int j = 0; j < 8; j++)
            #pragma unroll
            for (int r = 0; r < 4; r++) c[i][j][r] = 0.f;

    auto load_stage = [&](int s) {
        const uint32_t dst0 = sb + (uint32_t)(s & 1) * STAGE;
        const int c0b = s * 64;                       // 32 halves = 64 B
        #pragma unroll
        for (int pl = 0; pl < 4; ++pl) {
            const char* src = srcs[pl];
            #pragma unroll
            for (int j = 0; j < 2; ++j) {
                const int e = tid + 256 * j;          // 0..511
                const int row = e >> 2, q = e & 3;
                const char* g = src + (size_t)row * (K * 2) + c0b + q * 16;
                const uint32_t d = dst0 + pl * PLANE + row * ROWB + q * 16;
                CP_ASYNC16(d, g);
            }
        }
        CP_COMMIT();
    };

    // per-lane ldmatrix address offsets (bytes)
    const uint32_t aoff = (uint32_t)((lane & 15) * ROWB + (lane >> 4) * 16
                                     + wm * 32 * ROWB);
    const uint32_t boff = (uint32_t)(((lane & 7) + ((lane >> 4) << 3)) * ROWB
                                     + ((lane >> 3) & 1) * 16 + wn * 64 * ROWB);

    constexpr int NS = K / 32;
    load_stage(0);
    for (int s = 0; s < NS; ++s) {
        if (s + 1 < NS) {
            load_stage(s + 1);
            asm volatile("cp.async.wait_group 1;" ::: "memory");
        } else {
            asm volatile("cp.async.wait_group 0;" ::: "memory");
        }
        __syncthreads();

        const uint32_t base = sb + (uint32_t)(s & 1) * STAGE;
        #pragma unroll
        for (int k16 = 0; k16 < 2; ++k16) {
            const uint32_t kb = k16 * 32;
            uint32_t ah[2][4], al[2][4], bh[4][4], bl[4][4];
            #pragma unroll
            for (int mt = 0; mt < 2; ++mt) {
                ldsm4(base + 0 * PLANE + aoff + mt * 16 * ROWB + kb, ah[mt]);
                ldsm4(base + 1 * PLANE + aoff + mt * 16 * ROWB + kb, al[mt]);
            }
            #pragma unroll
            for (int np = 0; np < 4; ++np) {
                ldsm4(base + 2 * PLANE + boff + np * 16 * ROWB + kb, bh[np]);
                ldsm4(base + 3 * PLANE + boff + np * 16 * ROWB + kb, bl[np]);
            }
            // pass 1: Ah * Wh
            #pragma unroll
            for (int mt = 0; mt < 2; ++mt)
                #pragma unroll
                for (int nt = 0; nt < 8; ++nt)
                    mma16816(c[mt][nt], ah[mt],
                             bh[nt >> 1][(nt & 1) * 2], bh[nt >> 1][(nt & 1) * 2 + 1]);
            // pass 2: Ah * Wl
            #pragma unroll
            for (int mt = 0; mt < 2; ++mt)
                #pragma unroll
                for (int nt = 0; nt < 8; ++nt)
                    mma16816(c[mt][nt], ah[mt],
                             bl[nt >> 1][(nt & 1) * 2], bl[nt >> 1][(nt & 1) * 2 + 1]);
            // pass 3: Al * Wh
            #pragma unroll
            for (int mt = 0; mt < 2; ++mt)
                #pragma unroll
                for (int nt = 0; nt < 8; ++nt)
                    mma16816(c[mt][nt], al[mt],
                             bh[nt >> 1][(nt & 1) * 2], bh[nt >> 1][(nt & 1) * 2 + 1]);
        }
        __syncthreads();
    }

    // ------------------------------ epilogue -------------------------------
    const int gr = lane >> 2, gc = (lane & 3) << 1;
    #pragma unroll
    for (int mt = 0; mt < 2; ++mt) {
        #pragma unroll
        for (int nt = 0; nt < 8; ++nt) {
            const int n = n0 + wn * 64 + nt * 8 + gc;
            const float2 b2 = *reinterpret_cast<const float2*>(&bias[n]);
            #pragma unroll
            for (int rh = 0; rh < 2; ++rh) {
                const int m = m0 + wm * 32 + mt * 16 + gr + rh * 8;
                float vx = c[mt][nt][rh * 2 + 0] + b2.x;
                float vy = c[mt][nt][rh * 2 + 1] + b2.y;
                const size_t off = (size_t)m * N + n;
                if (EP == 1) {
                    const float2 r2 = *reinterpret_cast<const float2*>(&res[off]);
                    vx += r2.x; vy += r2.y;
                }
                if (EP <= 1) {
                    float2 o; o.x = vx; o.y = vy;
                    *reinterpret_cast<float2*>(&outf[off]) = o;
                } else {
                    vx = vx * normcdff(vx);
                    vy = vy * normcdff(vy);
                    __half hx, lx, hy, ly;
                    hsplit(vx, hx, lx);
                    hsplit(vy, hy, ly);
                    *reinterpret_cast<__half2*>(&oh[off]) = __halves2half2(hx, hy);
                    *reinterpret_cast<__half2*>(&ol[off]) = __halves2half2(lx, ly);
                }
            }
        }
    }
}

// =========================== transpose in/out ==============================
// x [b][c][p] fp32 -> xT fp32 [tok][c] + fp16 hi/lo
__global__ void __launch_bounds__(256) transpose_in(
    const float* __restrict__ x, float* __restrict__ xT,
    __half* __restrict__ xh, __half* __restrict__ xl)
{
    __shared__ float sm[64 * 65];
    const int b = blockIdx.z, c0 = blockIdx.y * 64, p0 = blockIdx.x * 64;
    const int tid = threadIdx.x;
    #pragma unroll
    for (int w = 0; w < 16; w++) {
        const int idx = tid + 256 * w;
        const int cl = idx >> 6, pl = idx & 63;
        sm[cl * 65 + pl] = x[((size_t)(b * 256 + c0 + cl)) * HW + p0 + pl];
    }
    __syncthreads();
    #pragma unroll
    for (int w = 0; w < 16; w++) {
        const int idx = tid + 256 * w;
        const int pl = idx >> 6, cl = idx & 63;
        const float v = sm[cl * 65 + pl];
        const size_t o = ((size_t)(b * HW + p0 + pl)) * 256 + c0 + cl;
        xT[o] = v;
        __half h, l;
        hsplit(v, h, l);
        xh[o] = h; xl[o] = l;
    }
}

// y [tok][c] fp32 -> out [b][c][p] fp32
__global__ void __launch_bounds__(256) transpose_out(
    const float* __restrict__ y, float* __restrict__ out)
{
    __shared__ float sm[64 * 65];
    const int b = blockIdx.z, c0 = blockIdx.y * 64, p0 = blockIdx.x * 64;
    const int tid = threadIdx.x;
    #pragma unroll
    for (int w = 0; w < 16; w++) {
        const int idx = tid + 256 * w;
        const int pl = idx >> 6, cl = idx & 63;
        sm[cl * 65 + pl] = y[((size_t)(b * HW + p0 + pl)) * 256 + c0 + cl];
    }
    __syncthreads();
    #pragma unroll
    for (int w = 0; w < 16; w++) {
        const int idx = tid + 256 * w;
        const int cl = idx >> 6, pl = idx & 63;
        out[((size_t)(b * 256 + c0 + cl)) * HW + p0 + pl] = sm[cl * 65 + pl];
    }
}

// ========================= dw conv 3x3 (token-major) =======================
// in t1 fp32 [tok][256] -> out fp16 hi/lo [tok][256]; BN2 folded (g_dwf/g_dbf).
__global__ void __launch_bounds__(256) dwconv_kernel(
    const float* __restrict__ in, __half* __restrict__ oh, __half* __restrict__ ol)
{
    const int by = blockIdx.x;             // b*64 + y
    const int b = by >> 6, y = by & 63;
    const int tid = threadIdx.x;
    const int c4 = tid & 63;               // float4 channel chunk
    const int xq = tid >> 6;               // 4 x-lanes

    float w[9][4];
    #pragma unroll
    for (int k = 0; k < 9; k++)
        #pragma unroll
        for (int cc = 0; cc < 4; cc++)
            w[k][cc] = g_dwf[(c4 * 4 + cc) * 9 + k];
    const float4 bs = *reinterpret_cast<const float4*>(&g_dbf[c4 * 4]);

    #pragma unroll 4
    for (int xi = 0; xi < 16; xi++) {
        const int x = xq * 16 + xi;
        float a0 = bs.x, a1 = bs.y, a2 = bs.z, a3 = bs.w;
        #pragma unroll
        for (int dy = -1; dy <= 1; dy++) {
            const int yy = y + dy;
            if (yy < 0 || yy > 63) continue;
            #pragma unroll
            for (int dx = -1; dx <= 1; dx++) {
                const int xx = x + dx;
                if (xx < 0 || xx > 63) continue;
                const int k = (dy + 1) * 3 + (dx + 1);
                const float4 v = *reinterpret_cast<const float4*>(
                    &in[((size_t)(b * HW + yy * 64 + xx)) * 256 + c4 * 4]);
                a0 = fmaf(w[k][0], v.x, a0);
                a1 = fmaf(w[k][1], v.y, a1);
                a2 = fmaf(w[k][2], v.z, a2);
                a3 = fmaf(w[k][3], v.w, a3);
            }
        }
        __half h0, l0, h1, l1, h2, l2, h3, l3;
        hsplit(a0, h0, l0); hsplit(a1, h1, l1);
        hsplit(a2, h2, l2); hsplit(a3, h3, l3);
        const size_t o = ((size_t)(b * HW + y * 64 + x)) * 256 + c4 * 4;
        uint2 uh, ul;
        __half2 t;
        t = __halves2half2(h0, h1); uh.x = *reinterpret_cast<uint32_t*>(&t);
        t = __halves2half2(h2, h3); uh.y = *reinterpret_cast<uint32_t*>(&t);
        t = __halves2half2(l0, l1); ul.x = *reinterpret_cast<uint32_t*>(&t);
        t = __halves2half2(l2, l3); ul.y = *reinterpret_cast<uint32_t*>(&t);
        *reinterpret_cast<uint2*>(&oh[o]) = uh;
        *reinterpret_cast<uint2*>(&ol[o]) = ul;
    }
}

// ===================== LayerNorm (stats fused) + split =====================
// x fp32 [tok][256] -> normalized fp16 hi/lo [tok][256] (gamma/beta folded
// into downstream weights).
__global__ void __launch_bounds__(256) ln_split(
    const float* __restrict__ x, __half* __restrict__ oh, __half* __restrict__ ol)
{
    const int warp = threadIdx.x >> 5, lane = threadIdx.x & 31;
    const int tok = blockIdx.x * 8 + warp;
    const float* row = x + (size_t)tok * 256;
    const float4 v0 = *reinterpret_cast<const float4*>(&row[lane * 8]);
    const float4 v1 = *reinterpret_cast<const float4*>(&row[lane * 8 + 4]);
    float s = v0.x + v0.y + v0.z + v0.w + v1.x + v1.y + v1.z + v1.w;
    float s2 = v0.x * v0.x + v0.y * v0.y + v0.z * v0.z + v0.w * v0.w
             + v1.x * v1.x + v1.y * v1.y + v1.z * v1.z + v1.w * v1.w;
    #pragma unroll
    for (int o = 16; o; o >>= 1) {
        s  += __shfl_xor_sync(0xffffffffu, s,  o);
        s2 += __shfl_xor_sync(0xffffffffu, s2, o);
    }
    const float mu = s * (1.f / 256.f);
    const float rs = rsqrtf(s2 * (1.f / 256.f) - mu * mu + EPS);

    float v[8] = {v0.x, v0.y, v0.z, v0.w, v1.x, v1.y, v1.z, v1.w};
    __half h[8], l[8];
    #pragma unroll
    for (int i = 0; i < 8; i++) hsplit((v[i] - mu) * rs, h[i], l[i]);
    uint4 uh, ul;
    __half2 t;
    t = __halves2half2(h[0], h[1]); uh.x = *reinterpret_cast<uint32_t*>(&t);
    t = __halves2half2(h[2], h[3]); uh.y = *reinterpret_cast<uint32_t*>(&t);
    t = __halves2half2(h[4], h[5]); uh.z = *reinterpret_cast<uint32_t*>(&t);
    t = __halves2half2(h[6], h[7]); uh.w = *reinterpret_cast<uint32_t*>(&t);
    t = __halves2half2(l[0], l[1]); ul.x = *reinterpret_cast<uint32_t*>(&t);
    t = __halves2half2(l[2], l[3]); ul.y = *reinterpret_cast<uint32_t*>(&t);
    t = __halves2half2(l[4], l[5]); ul.z = *reinterpret_cast<uint32_t*>(&t);
    t = __halves2half2(l[6], l[7]); ul.w = *reinterpret_cast<uint32_t*>(&t);
    *reinterpret_cast<uint4*>(&oh[(size_t)tok * 256 + lane * 8]) = uh;
    *reinterpret_cast<uint4*>(&ol[(size_t)tok * 256 + lane * 8]) = ul;
}

// ========================= window attention ================================
// qkv fp32 token-major [tok][768]; one block per (window, head).
// Output fp16 hi/lo token-major [tok][256].
__global__ void __launch_bounds__(256) attn_kernel(
    const float* __restrict__ qkv,
    __half* __restrict__ oh, __half* __restrict__ ol)
{
    __shared__ __align__(16) float bufQ[64 * 68];
    __shared__ __align__(16) float bufK[64 * 68];

    const int bx = blockIdx.x;
    const int head = bx & 3;
    const int win  = bx >> 2;
    const int b    = win >> 6;
    const int wrem = win & 63;
    const int pbase = b * HW + (wrem >> 3) * 512 + (wrem & 7) * 8;

    const int tid = threadIdx.x;
    const int tx = tid & 15, ty = tid >> 4;
    const int ty4 = ty << 2, tx4 = tx << 2;
    const int qo = head * 64, ko = 256 + head * 64, vo = 512 + head * 64;

    // load Q, K [t][d] (coalesced over d)
    for (int idx = tid; idx < 4096; idx += 256) {
        const int t = idx >> 6, d = idx & 63;
        const int p = pbase + (t >> 3) * 64 + (t & 7);
        bufQ[t * 68 + d] = qkv[(size_t)p * 768 + qo + d];
        bufK[t * 68 + d] = qkv[(size_t)p * 768 + ko + d];
    }
    __syncthreads();

    float s[4][4];
    #pragma unroll
    for (int i = 0; i < 4; i++)
        #pragma unroll
        for (int j = 0; j < 4; j++) s[i][j] = 0.f;

    for (int d = 0; d < 64; d += 4) {
        float4 q[4], k[4];
        #pragma unroll
        for (int i = 0; i < 4; i++)
            q[i] = *reinterpret_cast<const float4*>(&bufQ[(ty4 + i) * 68 + d]);
        #pragma unroll
        for (int j = 0; j < 4; j++)
            k[j] = *reinterpret_cast<const float4*>(&bufK[(tx4 + j) * 68 + d]);
        #pragma unroll
        for (int i = 0; i < 4; i++)
            #pragma unroll
            for (int j = 0; j < 4; j++) {
                s[i][j] = fmaf(q[i].x, k[j].x, s[i][j]);
                s[i][j] = fmaf(q[i].y, k[j].y, s[i][j]);
                s[i][j] = fmaf(q[i].z, k[j].z, s[i][j]);
                s[i][j] = fmaf(q[i].w, k[j].w, s[i][j]);
            }
    }

    const float scale = 0.125f;
    #pragma unroll
    for (int i = 0; i < 4; i++) {
        float mx = -1e30f;
        #pragma unroll
        for (int j = 0; j < 4; j++) { s[i][j] *= scale; mx = fmaxf(mx, s[i][j]); }
        #pragma unroll
        for (int off = 1; off < 16; off <<= 1)
            mx = fmaxf(mx, __shfl_xor_sync(0xffffffffu, mx, off));
        float sum = 0.f;
        #pragma unroll
        for (int j = 0; j < 4; j++) { s[i][j] = __expf(s[i][j] - mx); sum += s[i][j]; }
        #pragma unroll
        for (int off = 1; off < 16; off <<= 1)
            sum += __shfl_xor_sync(0xffffffffu, sum, off);
        const float inv = 1.f / sum;
        #pragma unroll
        for (int j = 0; j < 4; j++) s[i][j] *= inv;
    }
    __syncthreads();

    // P -> bufQ [n][m], V -> bufK [m][d]
    #pragma unroll
    for (int i = 0; i < 4; i++)
        #pragma unroll
        for (int j = 0; j < 4; j++)
            bufQ[(ty4 + i) * 68 + tx4 + j] = s[i][j];
    for (int idx = tid; idx < 4096; idx += 256) {
        const int m = idx >> 6, d = idx & 63;
        const int p = pbase + (m >> 3) * 64 + (m & 7);
        bufK[m * 68 + d] = qkv[(size_t)p * 768 + vo + d];
    }
    __syncthreads();

    float o[4][4];
    #pragma unroll
    for (int i = 0; i < 4; i++)
        #pragma unroll
        for (int j = 0; j < 4; j++) o[i][j] = 0.f;

    for (int m = 0; m < 64; m++) {
        float pv[4];
        #pragma unroll
        for (int i = 0; i < 4; i++) pv[i] = bufQ[(ty4 + i) * 68 + m];
        const float4 v4 = *reinterpret_cast<const float4*>(&bufK[m * 68 + tx4]);
        #pragma unroll
        for (int i = 0; i < 4; i++) {
            o[i][0] = fmaf(pv[i], v4.x, o[i][0]);
            o[i][1] = fmaf(pv[i], v4.y, o[i][1]);
            o[i][2] = fmaf(pv[i], v4.z, o[i][2]);
            o[i][3] = fmaf(pv[i], v4.w, o[i][3]);
        }
    }

    // store to fp16 hi/lo [p][256], c = head*64 + tx4 + j
    #pragma unroll
    for (int i = 0; i < 4; i++) {
        const int t = ty4 + i;
        const int p = pbase + (t >> 3) * 64 + (t & 7);
        __half h0, l0, h1, l1, h2, l2, h3, l3;
        hsplit(o[i][0], h0, l0); hsplit(o[i][1], h1, l1);
        hsplit(o[i][2], h2, l2); hsplit(o[i][3], h3, l3);
        const size_t off = (size_t)p * 256 + head * 64 + tx4;
        __half2 t01 = __halves2half2(h0, h1), t23 = __halves2half2(h2, h3);
        __half2 u01 = __halves2half2(l0, l1), u23 = __halves2half2(l2, l3);
        uint2 uh, ul;
        uh.x = *reinterpret_cast<uint32_t*>(&t01);
        uh.y = *reinterpret_cast<uint32_t*>(&t23);
        ul.x = *reinterpret_cast<uint32_t*>(&u01);
        ul.y = *reinterpret_cast<uint32_t*>(&u23);
        *reinterpret_cast<uint2*>(&oh[off]) = uh;
        *reinterpret_cast<uint2*>(&ol[off]) = ul;
    }
}

// =============================== launcher ==================================
extern "C" void kernel_launch(void* const* d_in, const int* in_sizes, int n_in,
                              void* d_out, int out_size)
{
    (void)in_sizes; (void)n_in; (void)out_size;
    const float* x       = (const float*)d_in[0];
    const float* conv1_w = (const float*)d_in[1];
    const float* conv1_b = (const float*)d_in[2];
    const float* bn1_g   = (const float*)d_in[3];
    const float* bn1_b   = (const float*)d_in[4];
    const float* bn1_m   = (const float*)d_in[5];
    const float* bn1_v   = (const float*)d_in[6];
    const float* dw_w    = (const float*)d_in[7];
    const float* dw_b    = (const float*)d_in[8];
    const float* bn2_g   = (const float*)d_in[9];
    const float* bn2_b   = (const float*)d_in[10];
    const float* bn2_m   = (const float*)d_in[11];
    const float* bn2_v   = (const float*)d_in[12];
    const float* conv3_w = (const float*)d_in[13];
    const float* conv3_b = (const float*)d_in[14];
    const float* ln1_g   = (const float*)d_in[15];
    const float* ln1_b   = (const float*)d_in[16];
    const float* qkv_w   = (const float*)d_in[17];
    const float* qkv_b   = (const float*)d_in[18];
    const float* proj_w  = (const float*)d_in[19];
    const float* proj_b  = (const float*)d_in[20];
    const float* ln2_g   = (const float*)d_in[21];
    const float* ln2_b   = (const float*)d_in[22];
    const float* mlp_w1  = (const float*)d_in[23];
    const float* mlp_b1  = (const float*)d_in[24];
    const float* mlp_w2  = (const float*)d_in[25];
    const float* mlp_b2  = (const float*)d_in[26];
    float* out = (float*)d_out;

    float *xT, *t1, *x1, *x2, *qkv, *y;
    float *b1f, *qkvbf, *m1bf;
    __half *xh, *xl, *t2h, *t2l, *x1nh, *x1nl, *obh, *obl, *x2nh, *x2nl;
    __half *hidh, *hidl;
    __half *w1h, *w1l, *w3h, *w3l, *wph, *wpl, *wqh, *wql, *m1h, *m1l, *w2h, *w2l;
    cudaGetSymbolAddress((void**)&xT,   g_xT);
    cudaGetSymbolAddress((void**)&t1,   g_t1);
    cudaGetSymbolAddress((void**)&x1,   g_x1);
    cudaGetSymbolAddress((void**)&x2,   g_x2);
    cudaGetSymbolAddress((void**)&qkv,  g_qkv);
    cudaGetSymbolAddress((void**)&y,    g_y);
    cudaGetSymbolAddress((void**)&xh,   g_xh);
    cudaGetSymbolAddress((void**)&xl,   g_xl);
    cudaGetSymbolAddress((void**)&t2h,  g_t2h);
    cudaGetSymbolAddress((void**)&t2l,  g_t2l);
    cudaGetSymbolAddress((void**)&x1nh, g_x1nh);
    cudaGetSymbolAddress((void**)&x1nl, g_x1nl);
    cudaGetSymbolAddress((void**)&obh,  g_obh);
    cudaGetSymbolAddress((void**)&obl,  g_obl);
    cudaGetSymbolAddress((void**)&x2nh, g_x2nh);
    cudaGetSymbolAddress((void**)&x2nl, g_x2nl);
    cudaGetSymbolAddress((void**)&hidh, g_hidh);
    cudaGetSymbolAddress((void**)&hidl, g_hidl);
    cudaGetSymbolAddress((void**)&w1h,  g_w1h);
    cudaGetSymbolAddress((void**)&w1l,  g_w1l);
    cudaGetSymbolAddress((void**)&w3h,  g_w3h);
    cudaGetSymbolAddress((void**)&w3l,  g_w3l);
    cudaGetSymbolAddress((void**)&wph,  g_wph);
    cudaGetSymbolAddress((void**)&wpl,  g_wpl);
    cudaGetSymbolAddress((void**)&wqh,  g_wqh);
    cudaGetSymbolAddress((void**)&wql,  g_wql);
    cudaGetSymbolAddress((void**)&m1h,  g_m1h);
    cudaGetSymbolAddress((void**)&m1l,  g_m1l);
    cudaGetSymbolAddress((void**)&w2h,  g_w2h);
    cudaGetSymbolAddress((void**)&w2l,  g_w2l);
    cudaGetSymbolAddress((void**)&b1f,   g_b1f);
    cudaGetSymbolAddress((void**)&qkvbf, g_qkvbf);
    cudaGetSymbolAddress((void**)&m1bf,  g_m1bf);

    cudaFuncSetAttribute(hgemm<256, 0>,
        cudaFuncAttributeMaxDynamicSharedMemorySize, GEMM_SMEM);
    cudaFuncSetAttribute(hgemm<256, 1>,
        cudaFuncAttributeMaxDynamicSharedMemorySize, GEMM_SMEM);
    cudaFuncSetAttribute(hgemm<256, 2>,
        cudaFuncAttributeMaxDynamicSharedMemorySize, GEMM_SMEM);
    cudaFuncSetAttribute(hgemm<1024, 1>,
        cudaFuncAttributeMaxDynamicSharedMemorySize, GEMM_SMEM);

    // 0) fold BN/LN into weights + fp16 split
    prep_kernel<<<1024, 256>>>(conv1_w, conv1_b, bn1_g, bn1_b, bn1_m, bn1_v,
                               dw_w, dw_b, bn2_g, bn2_b, bn2_m, bn2_v,
                               conv3_w, proj_w, mlp_w2,
                               qkv_w, qkv_b, ln1_g, ln1_b,
                               mlp_w1, mlp_b1, ln2_g, ln2_b);

    const dim3 gT(64, 4, 16);
    // 1) x -> xT fp32 + fp16 hi/lo (token-major)
    transpose_in<<<gT, 256>>>(x, xT, xh, xl);
    // 2) conv1 + BN1 -> t1 fp32
    hgemm<256, 0><<<dim3(2, 512), 256, GEMM_SMEM>>>(
        xh, xl, w1h, w1l, b1f, nullptr, t1, nullptr, nullptr, 256);
    // 3) dw3x3 + BN2 -> t2 fp16 hi/lo
    dwconv_kernel<<<1024, 256>>>(t1, t2h, t2l);
    // 4) conv3 + residual(xT) -> x1 fp32
    hgemm<256, 1><<<dim3(2, 512), 256, GEMM_SMEM>>>(
        t2h, t2l, w3h, w3l, conv3_b, xT, x1, nullptr, nullptr, 256);
    // 5) LN1 -> x1n fp16 hi/lo
    ln_split<<<8192, 256>>>(x1, x1nh, x1nl);
    // 6) QKV -> qkv fp32 [tok][768]
    hgemm<256, 0><<<dim3(6, 512), 256, GEMM_SMEM>>>(
        x1nh, x1nl, wqh, wql, qkvbf, nullptr, qkv, nullptr, nullptr, 768);
    // 7) window attention -> ob fp16 hi/lo
    attn_kernel<<<4096, 256>>>(qkv, obh, obl);
    // 8) proj + residual(x1) -> x2 fp32
    hgemm<256, 1><<<dim3(2, 512), 256, GEMM_SMEM>>>(
        obh, obl, wph, wpl, proj_b, x1, x2, nullptr, nullptr, 256);
    // 9) LN2 -> x2n fp16 hi/lo
    ln_split<<<8192, 256>>>(x2, x2nh, x2nl);
    // 10) MLP1 + GELU -> hid fp16 hi/lo [tok][1024]
    hgemm<256, 2><<<dim3(8, 512), 256, GEMM_SMEM>>>(
        x2nh, x2nl, m1h, m1l, m1bf, nullptr, nullptr, hidh, hidl, 1024);
    // 11) MLP2 + residual(x2) -> y fp32
    hgemm<1024, 1><<<dim3(2, 512), 256, GEMM_SMEM>>>(
        hidh, hidl, w2h, w2l, mlp_b2, x2, y, nullptr, nullptr, 256);
    // 12) y -> out [b][c][p]
    transpose_out<<<gT, 256>>>(y, out);
}

// round 5
// speedup vs baseline: 5.5999x; 1.8560x over previous
#include <cuda_runtime.h>
#include <cuda_fp16.h>
#include <math.h>
#include <stdint.h>
#include <stddef.h>

// ---------------------------------------------------------------------------
// TWSABlock round 5: token-major pipeline, pure fp16 single-pass GEMMs via
// mma.sync.m16n8k16 (error budget: all GEMM outputs are small branches on an
// exact fp32 residual stream). cp.async 2-stage, 2 CTAs/SM.
// ---------------------------------------------------------------------------

#define HW 4096
#define NB 16
#define CC 256
#define NTOK (NB * HW)          // 65536 tokens
#define EPS 1e-5f

// ============================ small helpers ================================
__device__ __forceinline__ uint32_t smem_u32(const void* p) {
    uint32_t a;
    asm("{ .reg .u64 t; cvta.to.shared.u64 t, %1; cvt.u32.u64 %0, t; }"
        : "=r"(a) : "l"(p));
    return a;
}
__device__ __forceinline__ void ldsm4(uint32_t addr, uint32_t* r) {
    asm volatile("ldmatrix.sync.aligned.m8n8.x4.shared.b16 {%0,%1,%2,%3}, [%4];"
                 : "=r"(r[0]), "=r"(r[1]), "=r"(r[2]), "=r"(r[3]) : "r"(addr));
}
__device__ __forceinline__ void mma16816(float* c, const uint32_t* a,
                                         uint32_t b0, uint32_t b1) {
    asm volatile(
        "mma.sync.aligned.m16n8k16.row.col.f32.f16.f16.f32 "
        "{%0,%1,%2,%3}, {%4,%5,%6,%7}, {%8,%9}, {%0,%1,%2,%3};"
        : "+f"(c[0]), "+f"(c[1]), "+f"(c[2]), "+f"(c[3])
        : "r"(a[0]), "r"(a[1]), "r"(a[2]), "r"(a[3]), "r"(b0), "r"(b1));
}
#define CP_ASYNC16(dst, src) \
    asm volatile("cp.async.cg.shared.global [%0], [%1], 16;" :: "r"(dst), "l"(src))
#define CP_COMMIT() asm volatile("cp.async.commit_group;" ::: "memory")

// ============================== scratch ====================================
// fp32 token-major activations (residual stream + LN inputs)
__device__ float g_xT[NTOK * CC];
__device__ float g_x1[NTOK * CC];
__device__ float g_x2[NTOK * CC];
__device__ float g_y [NTOK * CC];
// fp16 activations, token-major [p][c]
__device__ __half g_xh  [NTOK * CC];
__device__ __half g_t1h [NTOK * CC];
__device__ __half g_t2h [NTOK * CC];
__device__ __half g_x1nh[NTOK * CC];
__device__ __half g_qkvh[NTOK * 3 * CC];
__device__ __half g_obh [NTOK * CC];
__device__ __half g_x2nh[NTOK * CC];
__device__ __half g_hidh[NTOK * 4 * CC];
// folded weights [oc][k] fp16
__device__ __half g_w1h[CC * CC];
__device__ __half g_w3h[CC * CC];
__device__ __half g_wph[CC * CC];
__device__ __half g_wqh[3 * CC * CC];
__device__ __half g_m1h[4 * CC * CC];
__device__ __half g_w2h[CC * 4 * CC];
// biases / dw weights fp32
__device__ float g_b1f[CC];
__device__ float g_dwf[CC * 9];
__device__ float g_dbf[CC];
__device__ float g_qkvbf[3 * CC];
__device__ float g_m1bf[4 * CC];

// ============================= prep kernel =================================
__global__ void __launch_bounds__(256) prep_kernel(
    const float* __restrict__ conv1_w, const float* __restrict__ conv1_b,
    const float* __restrict__ bn1_g,  const float* __restrict__ bn1_b,
    const float* __restrict__ bn1_m,  const float* __restrict__ bn1_v,
    const float* __restrict__ dw_w,   const float* __restrict__ dw_b,
    const float* __restrict__ bn2_g,  const float* __restrict__ bn2_b,
    const float* __restrict__ bn2_m,  const float* __restrict__ bn2_v,
    const float* __restrict__ conv3_w,
    const float* __restrict__ proj_w,
    const float* __restrict__ mlp_w2,
    const float* __restrict__ qkv_w,  const float* __restrict__ qkv_b,
    const float* __restrict__ ln1_g,  const float* __restrict__ ln1_b,
    const float* __restrict__ mlp_w1, const float* __restrict__ mlp_b1,
    const float* __restrict__ ln2_g,  const float* __restrict__ ln2_b)
{
    __shared__ float red[8];
    const int r = blockIdx.x;
    const int tid = threadIdx.x;

    if (r < 256) {
        float inv1 = bn1_g[r] * rsqrtf(bn1_v[r] + EPS);
        g_w1h[r * 256 + tid] = __float2half_rn(conv1_w[r * 256 + tid] * inv1);
        g_w3h[r * 256 + tid] = __float2half_rn(conv3_w[r * 256 + tid]);
        g_wph[r * 256 + tid] = __float2half_rn(proj_w[r * 256 + tid]);
        #pragma unroll
        for (int k = 0; k < 4; k++)
            g_w2h[r * 1024 + tid + 256 * k] =
                __float2half_rn(mlp_w2[r * 1024 + tid + 256 * k]);
        if (tid == 0) g_b1f[r] = conv1_b[r] * inv1 + bn1_b[r] - bn1_m[r] * inv1;
        float inv2 = bn2_g[r] * rsqrtf(bn2_v[r] + EPS);
        if (tid < 9) g_dwf[r * 9 + tid] = dw_w[r * 9 + tid] * inv2;
        if (tid == 0) g_dbf[r] = dw_b[r] * inv2 + bn2_b[r] - bn2_m[r] * inv2;
    }
    if (r < 768) {
        float w = qkv_w[r * 256 + tid];
        g_wqh[r * 256 + tid] = __float2half_rn(w * ln1_g[tid]);
        float part = w * ln1_b[tid];
        #pragma unroll
        for (int o = 16; o; o >>= 1) part += __shfl_xor_sync(0xffffffffu, part, o);
        if ((tid & 31) == 0) red[tid >> 5] = part;
        __syncthreads();
        if (tid == 0) {
            float s = 0.f;
            #pragma unroll
            for (int w2 = 0; w2 < 8; w2++) s += red[w2];
            g_qkvbf[r] = qkv_b[r] + s;
        }
        __syncthreads();
    }
    if (r < 1024) {
        float w = mlp_w1[r * 256 + tid];
        g_m1h[r * 256 + tid] = __float2half_rn(w * ln2_g[tid]);
        float part = w * ln2_b[tid];
        #pragma unroll
        for (int o = 16; o; o >>= 1) part += __shfl_xor_sync(0xffffffffu, part, o);
        if ((tid & 31) == 0) red[tid >> 5] = part;
        __syncthreads();
        if (tid == 0) {
            float s = 0.f;
            #pragma unroll
            for (int w2 = 0; w2 < 8; w2++) s += red[w2];
            g_m1bf[r] = mlp_b1[r] + s;
        }
    }
}

// ========================= fp16 mma.sync GEMM ==============================
// C[m=token][n=oc] = sum_k A[m][k] * W[n][k]  (both K-major, row.col mma)
// Block tile 128x128, BK=32, 8 warps (4m x 2n), warp tile 32x64. Single pass.
constexpr int ROWB  = 80;                 // smem row stride bytes (32 halves + pad)
constexpr int PLANE = 128 * ROWB;         // 10240 B
constexpr int STAGE = 2 * PLANE;          // 20480 B  (A, W)
constexpr int GEMM_SMEM = 2 * STAGE;      // 40960 B

// EP: 0 bias -> fp16 ; 1 bias+res(fp32) -> fp32 ; 2 gelu(bias) -> fp16
template<int K, int EP>
__global__ void __launch_bounds__(256, 2) hgemm(
    const __half* __restrict__ A, const __half* __restrict__ W,
    const float* __restrict__ bias, const float* __restrict__ res,
    float* __restrict__ outf, __half* __restrict__ outh, int N)
{
    extern __shared__ __align__(128) char smem[];
    const uint32_t sb = smem_u32(smem);
    const int n0  = blockIdx.x * 128;
    const int m0  = blockIdx.y * 128;
    const int tid = threadIdx.x;
    const int lane = tid & 31, wid = tid >> 5;
    const int wm = wid >> 1, wn = wid & 1;

    const char* srcA = (const char*)(A + (size_t)m0 * K);
    const char* srcW = (const char*)(W + (size_t)n0 * K);

    float c[2][8][4];
    #pragma unroll
    for (int i = 0; i < 2; i++)
        #pragma unroll
        for (int j = 0; j < 8; j++)
            #pragma unroll
            for (int r = 0; r < 4; r++) c[i][j][r] = 0.f;

    auto load_stage = [&](int s) {
        const uint32_t dst0 = sb + (uint32_t)(s & 1) * STAGE;
        const int c0b = s * 64;                       // 32 halves = 64 B
        #pragma unroll
        for (int j = 0; j < 2; ++j) {
            const int e = tid + 256 * j;              // 0..511
            const int row = e >> 2, q = e & 3;
            CP_ASYNC16(dst0 + row * ROWB + q * 16,
                       srcA + (size_t)row * (K * 2) + c0b + q * 16);
            CP_ASYNC16(dst0 + PLANE + row * ROWB + q * 16,
                       srcW + (size_t)row * (K * 2) + c0b + q * 16);
        }
        CP_COMMIT();
    };

    const uint32_t aoff = (uint32_t)((lane & 15) * ROWB + (lane >> 4) * 16
                                     + wm * 32 * ROWB);
    const uint32_t boff = (uint32_t)(((lane & 7) + ((lane >> 4) << 3)) * ROWB
                                     + ((lane >> 3) & 1) * 16 + wn * 64 * ROWB);

    constexpr int NS = K / 32;
    load_stage(0);
    for (int s = 0; s < NS; ++s) {
        if (s + 1 < NS) {
            load_stage(s + 1);
            asm volatile("cp.async.wait_group 1;" ::: "memory");
        } else {
            asm volatile("cp.async.wait_group 0;" ::: "memory");
        }
        __syncthreads();

        const uint32_t base = sb + (uint32_t)(s & 1) * STAGE;
        #pragma unroll
        for (int k16 = 0; k16 < 2; ++k16) {
            const uint32_t kb = k16 * 32;
            uint32_t a[2][4], b[4][4];
            #pragma unroll
            for (int mt = 0; mt < 2; ++mt)
                ldsm4(base + aoff + mt * 16 * ROWB + kb, a[mt]);
            #pragma unroll
            for (int np = 0; np < 4; ++np)
                ldsm4(base + PLANE + boff + np * 16 * ROWB + kb, b[np]);
            #pragma unroll
            for (int mt = 0; mt < 2; ++mt)
                #pragma unroll
                for (int nt = 0; nt < 8; ++nt)
                    mma16816(c[mt][nt], a[mt],
                             b[nt >> 1][(nt & 1) * 2], b[nt >> 1][(nt & 1) * 2 + 1]);
        }
        __syncthreads();
    }

    // ------------------------------ epilogue -------------------------------
    const int gr = lane >> 2, gc = (lane & 3) << 1;
    #pragma unroll
    for (int mt = 0; mt < 2; ++mt) {
        #pragma unroll
        for (int nt = 0; nt < 8; ++nt) {
            const int n = n0 + wn * 64 + nt * 8 + gc;
            const float2 b2 = *reinterpret_cast<const float2*>(&bias[n]);
            #pragma unroll
            for (int rh = 0; rh < 2; ++rh) {
                const int m = m0 + wm * 32 + mt * 16 + gr + rh * 8;
                float vx = c[mt][nt][rh * 2 + 0] + b2.x;
                float vy = c[mt][nt][rh * 2 + 1] + b2.y;
                const size_t off = (size_t)m * N + n;
                if (EP == 1) {
                    const float2 r2 = *reinterpret_cast<const float2*>(&res[off]);
                    float2 o; o.x = vx + r2.x; o.y = vy + r2.y;
                    *reinterpret_cast<float2*>(&outf[off]) = o;
                } else {
                    if (EP == 2) {
                        vx = vx * normcdff(vx);
                        vy = vy * normcdff(vy);
                    }
                    *reinterpret_cast<__half2*>(&outh[off]) =
                        __halves2half2(__float2half_rn(vx), __float2half_rn(vy));
                }
            }
        }
    }
}

// =========================== transpose in/out ==============================
__global__ void __launch_bounds__(256) transpose_in(
    const float* __restrict__ x, float* __restrict__ xT, __half* __restrict__ xh)
{
    __shared__ float sm[64 * 65];
    const int b = blockIdx.z, c0 = blockIdx.y * 64, p0 = blockIdx.x * 64;
    const int tid = threadIdx.x;
    #pragma unroll
    for (int w = 0; w < 16; w++) {
        const int idx = tid + 256 * w;
        const int cl = idx >> 6, pl = idx & 63;
        sm[cl * 65 + pl] = x[((size_t)(b * 256 + c0 + cl)) * HW + p0 + pl];
    }
    __syncthreads();
    #pragma unroll
    for (int w = 0; w < 16; w++) {
        const int idx = tid + 256 * w;
        const int pl = idx >> 6, cl = idx & 63;
        const float v = sm[cl * 65 + pl];
        const size_t o = ((size_t)(b * HW + p0 + pl)) * 256 + c0 + cl;
        xT[o] = v;
        xh[o] = __float2half_rn(v);
    }
}

__global__ void __launch_bounds__(256) transpose_out(
    const float* __restrict__ y, float* __restrict__ out)
{
    __shared__ float sm[64 * 65];
    const int b = blockIdx.z, c0 = blockIdx.y * 64, p0 = blockIdx.x * 64;
    const int tid = threadIdx.x;
    #pragma unroll
    for (int w = 0; w < 16; w++) {
        const int idx = tid + 256 * w;
        const int pl = idx >> 6, cl = idx & 63;
        sm[cl * 65 + pl] = y[((size_t)(b * HW + p0 + pl)) * 256 + c0 + cl];
    }
    __syncthreads();
    #pragma unroll
    for (int w = 0; w < 16; w++) {
        const int idx = tid + 256 * w;
        const int cl = idx >> 6, pl = idx & 63;
        out[((size_t)(b * 256 + c0 + cl)) * HW + p0 + pl] = sm[cl * 65 + pl];
    }
}

// ========================= dw conv 3x3 (token-major) =======================
// in fp16 [tok][256] -> out fp16 [tok][256]; BN2 folded.
__global__ void __launch_bounds__(256) dwconv_kernel(
    const __half* __restrict__ in, __half* __restrict__ oh)
{
    const int by = blockIdx.x;             // b*64 + y
    const int b = by >> 6, y = by & 63;
    const int tid = threadIdx.x;
    const int c4 = tid & 63;               // 4-channel chunk
    const int xq = tid >> 6;               // 4 x-lanes

    float w[9][4];
    #pragma unroll
    for (int k = 0; k < 9; k++)
        #pragma unroll
        for (int cc = 0; cc < 4; cc++)
            w[k][cc] = g_dwf[(c4 * 4 + cc) * 9 + k];
    const float4 bs = *reinterpret_cast<const float4*>(&g_dbf[c4 * 4]);

    #pragma unroll 4
    for (int xi = 0; xi < 16; xi++) {
        const int x = xq * 16 + xi;
        float a0 = bs.x, a1 = bs.y, a2 = bs.z, a3 = bs.w;
        #pragma unroll
        for (int dy = -1; dy <= 1; dy++) {
            const int yy = y + dy;
            if (yy < 0 || yy > 63) continue;
            #pragma unroll
            for (int dx = -1; dx <= 1; dx++) {
                const int xx = x + dx;
                if (xx < 0 || xx > 63) continue;
                const int k = (dy + 1) * 3 + (dx + 1);
                const uint2 u = *reinterpret_cast<const uint2*>(
                    &in[((size_t)(b * HW + yy * 64 + xx)) * 256 + c4 * 4]);
                const float2 f01 = __half22float2(*reinterpret_cast<const __half2*>(&u.x));
                const float2 f23 = __half22float2(*reinterpret_cast<const __half2*>(&u.y));
                a0 = fmaf(w[k][0], f01.x, a0);
                a1 = fmaf(w[k][1], f01.y, a1);
                a2 = fmaf(w[k][2], f23.x, a2);
                a3 = fmaf(w[k][3], f23.y, a3);
            }
        }
        const size_t o = ((size_t)(b * HW + y * 64 + x)) * 256 + c4 * 4;
        uint2 uh;
        __half2 t;
        t = __halves2half2(__float2half_rn(a0), __float2half_rn(a1));
        uh.x = *reinterpret_cast<uint32_t*>(&t);
        t = __halves2half2(__float2half_rn(a2), __float2half_rn(a3));
        uh.y = *reinterpret_cast<uint32_t*>(&t);
        *reinterpret_cast<uint2*>(&oh[o]) = uh;
    }
}

// ===================== LayerNorm + fp16 convert ============================
__global__ void __launch_bounds__(256) ln_split(
    const float* __restrict__ x, __half* __restrict__ oh)
{
    const int warp = threadIdx.x >> 5, lane = threadIdx.x & 31;
    const int tok = blockIdx.x * 8 + warp;
    const float* row = x + (size_t)tok * 256;
    const float4 v0 = *reinterpret_cast<const float4*>(&row[lane * 8]);
    const float4 v1 = *reinterpret_cast<const float4*>(&row[lane * 8 + 4]);
    float s = v0.x + v0.y + v0.z + v0.w + v1.x + v1.y + v1.z + v1.w;
    float s2 = v0.x * v0.x + v0.y * v0.y + v0.z * v0.z + v0.w * v0.w
             + v1.x * v1.x + v1.y * v1.y + v1.z * v1.z + v1.w * v1.w;
    #pragma unroll
    for (int o = 16; o; o >>= 1) {
        s  += __shfl_xor_sync(0xffffffffu, s,  o);
        s2 += __shfl_xor_sync(0xffffffffu, s2, o);
    }
    const float mu = s * (1.f / 256.f);
    const float rs = rsqrtf(s2 * (1.f / 256.f) - mu * mu + EPS);

    float v[8] = {v0.x, v0.y, v0.z, v0.w, v1.x, v1.y, v1.z, v1.w};
    uint4 uh;
    __half2 t;
    t = __halves2half2(__float2half_rn((v[0] - mu) * rs),
                       __float2half_rn((v[1] - mu) * rs));
    uh.x = *reinterpret_cast<uint32_t*>(&t);
    t = __halves2half2(__float2half_rn((v[2] - mu) * rs),
                       __float2half_rn((v[3] - mu) * rs));
    uh.y = *reinterpret_cast<uint32_t*>(&t);
    t = __halves2half2(__float2half_rn((v[4] - mu) * rs),
                       __float2half_rn((v[5] - mu) * rs));
    uh.z = *reinterpret_cast<uint32_t*>(&t);
    t = __halves2half2(__float2half_rn((v[6] - mu) * rs),
                       __float2half_rn((v[7] - mu) * rs));
    uh.w = *reinterpret_cast<uint32_t*>(&t);
    *reinterpret_cast<uint4*>(&oh[(size_t)tok * 256 + lane * 8]) = uh;
}

// ========================= window attention ================================
// qkv fp16 token-major [tok][768]; one block per (window, head).
__global__ void __launch_bounds__(256) attn_kernel(
    const __half* __restrict__ qkv, __half* __restrict__ oh)
{
    __shared__ __align__(16) float bufQ[64 * 68];
    __shared__ __align__(16) float bufK[64 * 68];

    const int bx = blockIdx.x;
    const int head = bx & 3;
    const int win  = bx >> 2;
    const int b    = win >> 6;
    const int wrem = win & 63;
    const int pbase = b * HW + (wrem >> 3) * 512 + (wrem & 7) * 8;

    const int tid = threadIdx.x;
    const int tx = tid & 15, ty = tid >> 4;
    const int ty4 = ty << 2, tx4 = tx << 2;
    const int qo = head * 64, ko = 256 + head * 64, vo = 512 + head * 64;

    // load Q, K [t][d]
    for (int idx = tid; idx < 2048; idx += 256) {
        const int t = idx >> 5, d0 = (idx & 31) * 2;
        const int p = pbase + (t >> 3) * 64 + (t & 7);
        const float2 q2 = __half22float2(
            *reinterpret_cast<const __half2*>(&qkv[(size_t)p * 768 + qo + d0]));
        const float2 k2 = __half22float2(
            *reinterpret_cast<const __half2*>(&qkv[(size_t)p * 768 + ko + d0]));
        bufQ[t * 68 + d0] = q2.x; bufQ[t * 68 + d0 + 1] = q2.y;
        bufK[t * 68 + d0] = k2.x; bufK[t * 68 + d0 + 1] = k2.y;
    }
    __syncthreads();

    float s[4][4];
    #pragma unroll
    for (int i = 0; i < 4; i++)
        #pragma unroll
        for (int j = 0; j < 4; j++) s[i][j] = 0.f;

    for (int d = 0; d < 64; d += 4) {
        float4 q[4], k[4];
        #pragma unroll
        for (int i = 0; i < 4; i++)
            q[i] = *reinterpret_cast<const float4*>(&bufQ[(ty4 + i) * 68 + d]);
        #pragma unroll
        for (int j = 0; j < 4; j++)
            k[j] = *reinterpret_cast<const float4*>(&bufK[(tx4 + j) * 68 + d]);
        #pragma unroll
        for (int i = 0; i < 4; i++)
            #pragma unroll
            for (int j = 0; j < 4; j++) {
                s[i][j] = fmaf(q[i].x, k[j].x, s[i][j]);
                s[i][j] = fmaf(q[i].y, k[j].y, s[i][j]);
                s[i][j] = fmaf(q[i].z, k[j].z, s[i][j]);
                s[i][j] = fmaf(q[i].w, k[j].w, s[i][j]);
            }
    }

    const float scale = 0.125f;
    #pragma unroll
    for (int i = 0; i < 4; i++) {
        float mx = -1e30f;
        #pragma unroll
        for (int j = 0; j < 4; j++) { s[i][j] *= scale; mx = fmaxf(mx, s[i][j]); }
        #pragma unroll
        for (int off = 1; off < 16; off <<= 1)
            mx = fmaxf(mx, __shfl_xor_sync(0xffffffffu, mx, off));
        float sum = 0.f;
        #pragma unroll
        for (int j = 0; j < 4; j++) { s[i][j] = __expf(s[i][j] - mx); sum += s[i][j]; }
        #pragma unroll
        for (int off = 1; off < 16; off <<= 1)
            sum += __shfl_xor_sync(0xffffffffu, sum, off);
        const float inv = 1.f / sum;
        #pragma unroll
        for (int j = 0; j < 4; j++) s[i][j] *= inv;
    }
    __syncthreads();

    // P -> bufQ [n][m], V -> bufK [m][d]
    #pragma unroll
    for (int i = 0; i < 4; i++)
        #pragma unroll
        for (int j = 0; j < 4; j++)
            bufQ[(ty4 + i) * 68 + tx4 + j] = s[i][j];
    for (int idx = tid; idx < 2048; idx += 256) {
        const int m = idx >> 5, d0 = (idx & 31) * 2;
        const int p = pbase + (m >> 3) * 64 + (m & 7);
        const float2 v2 = __half22float2(
            *reinterpret_cast<const __half2*>(&qkv[(size_t)p * 768 + vo + d0]));
        bufK[m * 68 + d0] = v2.x; bufK[m * 68 + d0 + 1] = v2.y;
    }
    __syncthreads();

    float o[4][4];
    #pragma unroll
    for (int i = 0; i < 4; i++)
        #pragma unroll
        for (int j = 0; j < 4; j++) o[i][j] = 0.f;

    for (int m = 0; m < 64; m++) {
        float pv[4];
        #pragma unroll
        for (int i = 0; i < 4; i++) pv[i] = bufQ[(ty4 + i) * 68 + m];
        const float4 v4 = *reinterpret_cast<const float4*>(&bufK[m * 68 + tx4]);
        #pragma unroll
        for (int i = 0; i < 4; i++) {
            o[i][0] = fmaf(pv[i], v4.x, o[i][0]);
            o[i][1] = fmaf(pv[i], v4.y, o[i][1]);
            o[i][2] = fmaf(pv[i], v4.z, o[i][2]);
            o[i][3] = fmaf(pv[i], v4.w, o[i][3]);
        }
    }

    #pragma unroll
    for (int i = 0; i < 4; i++) {
        const int t = ty4 + i;
        const int p = pbase + (t >> 3) * 64 + (t & 7);
        const size_t off = (size_t)p * 256 + head * 64 + tx4;
        __half2 t01 = __halves2half2(__float2half_rn(o[i][0]), __float2half_rn(o[i][1]));
        __half2 t23 = __halves2half2(__float2half_rn(o[i][2]), __float2half_rn(o[i][3]));
        uint2 uh;
        uh.x = *reinterpret_cast<uint32_t*>(&t01);
        uh.y = *reinterpret_cast<uint32_t*>(&t23);
        *reinterpret_cast<uint2*>(&oh[off]) = uh;
    }
}

// =============================== launcher ==================================
extern "C" void kernel_launch(void* const* d_in, const int* in_sizes, int n_in,
                              void* d_out, int out_size)
{
    (void)in_sizes; (void)n_in; (void)out_size;
    const float* x       = (const float*)d_in[0];
    const float* conv1_w = (const float*)d_in[1];
    const float* conv1_b = (const float*)d_in[2];
    const float* bn1_g   = (const float*)d_in[3];
    const float* bn1_b   = (const float*)d_in[4];
    const float* bn1_m   = (const float*)d_in[5];
    const float* bn1_v   = (const float*)d_in[6];
    const float* dw_w    = (const float*)d_in[7];
    const float* dw_b    = (const float*)d_in[8];
    const float* bn2_g   = (const float*)d_in[9];
    const float* bn2_b   = (const float*)d_in[10];
    const float* bn2_m   = (const float*)d_in[11];
    const float* bn2_v   = (const float*)d_in[12];
    const float* conv3_w = (const float*)d_in[13];
    const float* conv3_b = (const float*)d_in[14];
    const float* ln1_g   = (const float*)d_in[15];
    const float* ln1_b   = (const float*)d_in[16];
    const float* qkv_w   = (const float*)d_in[17];
    const float* qkv_b   = (const float*)d_in[18];
    const float* proj_w  = (const float*)d_in[19];
    const float* proj_b  = (const float*)d_in[20];
    const float* ln2_g   = (const float*)d_in[21];
    const float* ln2_b   = (const float*)d_in[22];
    const float* mlp_w1  = (const float*)d_in[23];
    const float* mlp_b1  = (const float*)d_in[24];
    const float* mlp_w2  = (const float*)d_in[25];
    const float* mlp_b2  = (const float*)d_in[26];
    float* out = (float*)d_out;

    float *xT, *x1, *x2, *y, *b1f, *qkvbf, *m1bf;
    __half *xh, *t1h, *t2h, *x1nh, *qkvh, *obh, *x2nh, *hidh;
    __half *w1h, *w3h, *wph, *wqh, *m1h, *w2h;
    cudaGetSymbolAddress((void**)&xT,   g_xT);
    cudaGetSymbolAddress((void**)&x1,   g_x1);
    cudaGetSymbolAddress((void**)&x2,   g_x2);
    cudaGetSymbolAddress((void**)&y,    g_y);
    cudaGetSymbolAddress((void**)&xh,   g_xh);
    cudaGetSymbolAddress((void**)&t1h,  g_t1h);
    cudaGetSymbolAddress((void**)&t2h,  g_t2h);
    cudaGetSymbolAddress((void**)&x1nh, g_x1nh);
    cudaGetSymbolAddress((void**)&qkvh, g_qkvh);
    cudaGetSymbolAddress((void**)&obh,  g_obh);
    cudaGetSymbolAddress((void**)&x2nh, g_x2nh);
    cudaGetSymbolAddress((void**)&hidh, g_hidh);
    cudaGetSymbolAddress((void**)&w1h,  g_w1h);
    cudaGetSymbolAddress((void**)&w3h,  g_w3h);
    cudaGetSymbolAddress((void**)&wph,  g_wph);
    cudaGetSymbolAddress((void**)&wqh,  g_wqh);
    cudaGetSymbolAddress((void**)&m1h,  g_m1h);
    cudaGetSymbolAddress((void**)&w2h,  g_w2h);
    cudaGetSymbolAddress((void**)&b1f,   g_b1f);
    cudaGetSymbolAddress((void**)&qkvbf, g_qkvbf);
    cudaGetSymbolAddress((void**)&m1bf,  g_m1bf);

    cudaFuncSetAttribute(hgemm<256, 0>,
        cudaFuncAttributeMaxDynamicSharedMemorySize, GEMM_SMEM);
    cudaFuncSetAttribute(hgemm<256, 1>,
        cudaFuncAttributeMaxDynamicSharedMemorySize, GEMM_SMEM);
    cudaFuncSetAttribute(hgemm<256, 2>,
        cudaFuncAttributeMaxDynamicSharedMemorySize, GEMM_SMEM);
    cudaFuncSetAttribute(hgemm<1024, 1>,
        cudaFuncAttributeMaxDynamicSharedMemorySize, GEMM_SMEM);

    // 0) fold BN/LN into weights, fp16 convert
    prep_kernel<<<1024, 256>>>(conv1_w, conv1_b, bn1_g, bn1_b, bn1_m, bn1_v,
                               dw_w, dw_b, bn2_g, bn2_b, bn2_m, bn2_v,
                               conv3_w, proj_w, mlp_w2,
                               qkv_w, qkv_b, ln1_g, ln1_b,
                               mlp_w1, mlp_b1, ln2_g, ln2_b);

    const dim3 gT(64, 4, 16);
    // 1) x -> xT fp32 + xh fp16 (token-major)
    transpose_in<<<gT, 256>>>(x, xT, xh);
    // 2) conv1 + BN1 -> t1 fp16
    hgemm<256, 0><<<dim3(2, 512), 256, GEMM_SMEM>>>(
        xh, w1h, b1f, nullptr, nullptr, t1h, 256);
    // 3) dw3x3 + BN2 -> t2 fp16
    dwconv_kernel<<<1024, 256>>>(t1h, t2h);
    // 4) conv3 + residual(xT) -> x1 fp32
    hgemm<256, 1><<<dim3(2, 512), 256, GEMM_SMEM>>>(
        t2h, w3h, conv3_b, xT, x1, nullptr, 256);
    // 5) LN1 -> x1n fp16
    ln_split<<<8192, 256>>>(x1, x1nh);
    // 6) QKV -> qkv fp16 [tok][768]
    hgemm<256, 0><<<dim3(6, 512), 256, GEMM_SMEM>>>(
        x1nh, wqh, qkvbf, nullptr, nullptr, qkvh, 768);
    // 7) window attention -> ob fp16
    attn_kernel<<<4096, 256>>>(qkvh, obh);
    // 8) proj + residual(x1) -> x2 fp32
    hgemm<256, 1><<<dim3(2, 512), 256, GEMM_SMEM>>>(
        obh, wph, proj_b, x1, x2, nullptr, 256);
    // 9) LN2 -> x2n fp16
    ln_split<<<8192, 256>>>(x2, x2nh);
    // 10) MLP1 + GELU -> hid fp16 [tok][1024]
    hgemm<256, 2><<<dim3(8, 512), 256, GEMM_SMEM>>>(
        x2nh, m1h, m1bf, nullptr, nullptr, hidh, 1024);
    // 11) MLP2 + residual(x2) -> y fp32
    hgemm<1024, 1><<<dim3(2, 512), 256, GEMM_SMEM>>>(
        hidh, w2h, mlp_b2, x2, y, nullptr, 256);
    // 12) y -> out [b][c][p]
    transpose_out<<<gT, 256>>>(y, out);
}

// round 6
// speedup vs baseline: 6.8280x; 1.2193x over previous
#include <cuda_runtime.h>
#include <cuda_fp16.h>
#include <math.h>
#include <stdint.h>
#include <stddef.h>

// ---------------------------------------------------------------------------
// TWSABlock round 6: fp16 mma.sync everywhere (GEMMs + window attention),
// NCHW<->token-major transposes fused into GEMM epilogues, sliding-window
// dwconv. fp32 residual stream preserved end-to-end.
// ---------------------------------------------------------------------------

#define HW 4096
#define NB 16
#define CC 256
#define NTOK (NB * HW)
#define EPS 1e-5f

// ============================ small helpers ================================
__device__ __forceinline__ uint32_t smem_u32(const void* p) {
    uint32_t a;
    asm("{ .reg .u64 t; cvta.to.shared.u64 t, %1; cvt.u32.u64 %0, t; }"
        : "=r"(a) : "l"(p));
    return a;
}
__device__ __forceinline__ void ldsm4(uint32_t addr, uint32_t* r) {
    asm volatile("ldmatrix.sync.aligned.m8n8.x4.shared.b16 {%0,%1,%2,%3}, [%4];"
                 : "=r"(r[0]), "=r"(r[1]), "=r"(r[2]), "=r"(r[3]) : "r"(addr));
}
__device__ __forceinline__ void mma16816(float* c, const uint32_t* a,
                                         uint32_t b0, uint32_t b1) {
    asm volatile(
        "mma.sync.aligned.m16n8k16.row.col.f32.f16.f16.f32 "
        "{%0,%1,%2,%3}, {%4,%5,%6,%7}, {%8,%9}, {%0,%1,%2,%3};"
        : "+f"(c[0]), "+f"(c[1]), "+f"(c[2]), "+f"(c[3])
        : "r"(a[0]), "r"(a[1]), "r"(a[2]), "r"(a[3]), "r"(b0), "r"(b1));
}
__device__ __forceinline__ uint32_t packh2(float a, float b) {
    __half2 t = __halves2half2(__float2half_rn(a), __float2half_rn(b));
    return *reinterpret_cast<uint32_t*>(&t);
}
#define CP_ASYNC16(dst, src) \
    asm volatile("cp.async.cg.shared.global [%0], [%1], 16;" :: "r"(dst), "l"(src))
#define CP_COMMIT() asm volatile("cp.async.commit_group;" ::: "memory")

// ============================== scratch ====================================
__device__ float g_x1[NTOK * CC];
__device__ float g_x2[NTOK * CC];
__device__ __half g_xh  [NTOK * CC];
__device__ __half g_t1h [NTOK * CC];
__device__ __half g_t2h [NTOK * CC];
__device__ __half g_x1nh[NTOK * CC];
__device__ __half g_qkvh[NTOK * 3 * CC];
__device__ __half g_obh [NTOK * CC];
__device__ __half g_x2nh[NTOK * CC];
__device__ __half g_hidh[NTOK * 4 * CC];
__device__ __half g_w1h[CC * CC];
__device__ __half g_w3h[CC * CC];
__device__ __half g_wph[CC * CC];
__device__ __half g_wqh[3 * CC * CC];
__device__ __half g_m1h[4 * CC * CC];
__device__ __half g_w2h[CC * 4 * CC];
__device__ float g_b1f[CC];
__device__ float g_dwf[CC * 9];
__device__ float g_dbf[CC];
__device__ float g_qkvbf[3 * CC];
__device__ float g_m1bf[4 * CC];

// ============================= prep kernel =================================
__global__ void __launch_bounds__(256) prep_kernel(
    const float* __restrict__ conv1_w, const float* __restrict__ conv1_b,
    const float* __restrict__ bn1_g,  const float* __restrict__ bn1_b,
    const float* __restrict__ bn1_m,  const float* __restrict__ bn1_v,
    const float* __restrict__ dw_w,   const float* __restrict__ dw_b,
    const float* __restrict__ bn2_g,  const float* __restrict__ bn2_b,
    const float* __restrict__ bn2_m,  const float* __restrict__ bn2_v,
    const float* __restrict__ conv3_w,
    const float* __restrict__ proj_w,
    const float* __restrict__ mlp_w2,
    const float* __restrict__ qkv_w,  const float* __restrict__ qkv_b,
    const float* __restrict__ ln1_g,  const float* __restrict__ ln1_b,
    const float* __restrict__ mlp_w1, const float* __restrict__ mlp_b1,
    const float* __restrict__ ln2_g,  const float* __restrict__ ln2_b)
{
    __shared__ float red[8];
    const int r = blockIdx.x;
    const int tid = threadIdx.x;

    if (r < 256) {
        float inv1 = bn1_g[r] * rsqrtf(bn1_v[r] + EPS);
        g_w1h[r * 256 + tid] = __float2half_rn(conv1_w[r * 256 + tid] * inv1);
        g_w3h[r * 256 + tid] = __float2half_rn(conv3_w[r * 256 + tid]);
        g_wph[r * 256 + tid] = __float2half_rn(proj_w[r * 256 + tid]);
        #pragma unroll
        for (int k = 0; k < 4; k++)
            g_w2h[r * 1024 + tid + 256 * k] =
                __float2half_rn(mlp_w2[r * 1024 + tid + 256 * k]);
        if (tid == 0) g_b1f[r] = conv1_b[r] * inv1 + bn1_b[r] - bn1_m[r] * inv1;
        float inv2 = bn2_g[r] * rsqrtf(bn2_v[r] + EPS);
        if (tid < 9) g_dwf[r * 9 + tid] = dw_w[r * 9 + tid] * inv2;
        if (tid == 0) g_dbf[r] = dw_b[r] * inv2 + bn2_b[r] - bn2_m[r] * inv2;
    }
    if (r < 768) {
        float w = qkv_w[r * 256 + tid];
        g_wqh[r * 256 + tid] = __float2half_rn(w * ln1_g[tid]);
        float part = w * ln1_b[tid];
        #pragma unroll
        for (int o = 16; o; o >>= 1) part += __shfl_xor_sync(0xffffffffu, part, o);
        if ((tid & 31) == 0) red[tid >> 5] = part;
        __syncthreads();
        if (tid == 0) {
            float s = 0.f;
            #pragma unroll
            for (int w2 = 0; w2 < 8; w2++) s += red[w2];
            g_qkvbf[r] = qkv_b[r] + s;
        }
        __syncthreads();
    }
    if (r < 1024) {
        float w = mlp_w1[r * 256 + tid];
        g_m1h[r * 256 + tid] = __float2half_rn(w * ln2_g[tid]);
        float part = w * ln2_b[tid];
        #pragma unroll
        for (int o = 16; o; o >>= 1) part += __shfl_xor_sync(0xffffffffu, part, o);
        if ((tid & 31) == 0) red[tid >> 5] = part;
        __syncthreads();
        if (tid == 0) {
            float s = 0.f;
            #pragma unroll
            for (int w2 = 0; w2 < 8; w2++) s += red[w2];
            g_m1bf[r] = mlp_b1[r] + s;
        }
    }
}

// ========================= fp16 mma.sync GEMM ==============================
// C[m=token][n=oc] = sum_k A[m][k] * W[n][k]
// Block 128x128, BK=32, 8 warps (4m x 2n), warp tile 32x64.
constexpr int ROWB  = 80;
constexpr int PLANE = 128 * ROWB;
constexpr int STAGE = 2 * PLANE;
constexpr int GEMM_SMEM = 2 * STAGE;      // 40960 B

// EP: 0 bias->fp16 ; 1 bias+res(tok fp32)->fp32 tok ; 2 gelu(bias)->fp16 ;
//     3 bias+res(NCHW fp32 via smem transpose)->fp32 tok ;
//     4 bias+res(tok fp32) -> NCHW fp32 out (smem transpose)
template<int K, int EP>
__global__ void __launch_bounds__(256, 2) hgemm(
    const __half* __restrict__ A, const __half* __restrict__ W,
    const float* __restrict__ bias, const float* __restrict__ res,
    float* __restrict__ outf, __half* __restrict__ outh, int N)
{
    extern __shared__ __align__(128) char smem[];
    const uint32_t sb = smem_u32(smem);
    const int n0  = blockIdx.x * 128;
    const int m0  = blockIdx.y * 128;
    const int tid = threadIdx.x;
    const int lane = tid & 31, wid = tid >> 5;
    const int wm = wid >> 1, wn = wid & 1;

    const char* srcA = (const char*)(A + (size_t)m0 * K);
    const char* srcW = (const char*)(W + (size_t)n0 * K);

    float c[2][8][4];
    #pragma unroll
    for (int i = 0; i < 2; i++)
        #pragma unroll
        for (int j = 0; j < 8; j++)
            #pragma unroll
            for (int r = 0; r < 4; r++) c[i][j][r] = 0.f;

    auto load_stage = [&](int s) {
        const uint32_t dst0 = sb + (uint32_t)(s & 1) * STAGE;
        const int c0b = s * 64;
        #pragma unroll
        for (int j = 0; j < 2; ++j) {
            const int e = tid + 256 * j;
            const int row = e >> 2, q = e & 3;
            CP_ASYNC16(dst0 + row * ROWB + q * 16,
                       srcA + (size_t)row * (K * 2) + c0b + q * 16);
            CP_ASYNC16(dst0 + PLANE + row * ROWB + q * 16,
                       srcW + (size_t)row * (K * 2) + c0b + q * 16);
        }
        CP_COMMIT();
    };

    const uint32_t aoff = (uint32_t)((lane & 15) * ROWB + (lane >> 4) * 16
                                     + wm * 32 * ROWB);
    const uint32_t boff = (uint32_t)(((lane & 7) + ((lane >> 4) << 3)) * ROWB
                                     + ((lane >> 3) & 1) * 16 + wn * 64 * ROWB);

    constexpr int NS = K / 32;
    load_stage(0);
    for (int s = 0; s < NS; ++s) {
        if (s + 1 < NS) {
            load_stage(s + 1);
            asm volatile("cp.async.wait_group 1;" ::: "memory");
        } else {
            asm volatile("cp.async.wait_group 0;" ::: "memory");
        }
        __syncthreads();

        const uint32_t base = sb + (uint32_t)(s & 1) * STAGE;
        #pragma unroll
        for (int k16 = 0; k16 < 2; ++k16) {
            const uint32_t kb = k16 * 32;
            uint32_t a[2][4], b[4][4];
            #pragma unroll
            for (int mt = 0; mt < 2; ++mt)
                ldsm4(base + aoff + mt * 16 * ROWB + kb, a[mt]);
            #pragma unroll
            for (int np = 0; np < 4; ++np)
                ldsm4(base + PLANE + boff + np * 16 * ROWB + kb, b[np]);
            #pragma unroll
            for (int mt = 0; mt < 2; ++mt)
                #pragma unroll
                for (int nt = 0; nt < 8; ++nt)
                    mma16816(c[mt][nt], a[mt],
                             b[nt >> 1][(nt & 1) * 2], b[nt >> 1][(nt & 1) * 2 + 1]);
        }
        __syncthreads();
    }

    // ------------------------------ epilogue -------------------------------
    const int gr = lane >> 2, gc = (lane & 3) << 1;

    if (EP <= 2) {
        #pragma unroll
        for (int mt = 0; mt < 2; ++mt) {
            #pragma unroll
            for (int nt = 0; nt < 8; ++nt) {
                const int n = n0 + wn * 64 + nt * 8 + gc;
                const float2 b2 = *reinterpret_cast<const float2*>(&bias[n]);
                #pragma unroll
                for (int rh = 0; rh < 2; ++rh) {
                    const int m = m0 + wm * 32 + mt * 16 + gr + rh * 8;
                    float vx = c[mt][nt][rh * 2 + 0] + b2.x;
                    float vy = c[mt][nt][rh * 2 + 1] + b2.y;
                    const size_t off = (size_t)m * N + n;
                    if (EP == 1) {
                        const float2 r2 = *reinterpret_cast<const float2*>(&res[off]);
                        float2 o; o.x = vx + r2.x; o.y = vy + r2.y;
                        *reinterpret_cast<float2*>(&outf[off]) = o;
                    } else {
                        if (EP == 2) {
                            vx = vx * normcdff(vx);
                            vy = vy * normcdff(vy);
                        }
                        *reinterpret_cast<__half2*>(&outh[off]) =
                            __halves2half2(__float2half_rn(vx), __float2half_rn(vy));
                    }
                }
            }
        }
    } else if (EP == 3) {
        // residual from NCHW res[b][c][p]; output fp32 token-major
        float* Rs = reinterpret_cast<float*>(smem);   // [64][132] fp32
        const int bb = m0 >> 12, p0 = m0 & 4095;
        #pragma unroll
        for (int nh = 0; nh < 2; ++nh) {
            __syncthreads();
            for (int e = tid; e < 2048; e += 256) {
                const int row = e >> 5, q = e & 31;
                *reinterpret_cast<float4*>(&Rs[row * 132 + q * 4]) =
                    *reinterpret_cast<const float4*>(
                        &res[((size_t)(bb * 256 + n0 + nh * 64 + row)) * HW + p0 + q * 4]);
            }
            __syncthreads();
            if (wn == nh) {
                #pragma unroll
                for (int mt = 0; mt < 2; ++mt) {
                    #pragma unroll
                    for (int nt = 0; nt < 8; ++nt) {
                        const int nl = nt * 8 + gc;
                        const int n = n0 + wn * 64 + nl;
                        const float2 b2 = *reinterpret_cast<const float2*>(&bias[n]);
                        #pragma unroll
                        for (int rh = 0; rh < 2; ++rh) {
                            const int ml = wm * 32 + mt * 16 + gr + rh * 8;
                            float2 o;
                            o.x = c[mt][nt][rh * 2 + 0] + b2.x + Rs[nl * 132 + ml];
                            o.y = c[mt][nt][rh * 2 + 1] + b2.y + Rs[(nl + 1) * 132 + ml];
                            *reinterpret_cast<float2*>(&outf[(size_t)(m0 + ml) * 256 + n]) = o;
                        }
                    }
                }
            }
        }
    } else {  // EP == 4: residual token-major fp32, output NCHW fp32
        float* Cs = reinterpret_cast<float*>(smem);   // [64][132] fp32
        const int bb = m0 >> 12, p0 = m0 & 4095;
        #pragma unroll
        for (int nh = 0; nh < 2; ++nh) {
            __syncthreads();
            if (wn == nh) {
                #pragma unroll
                for (int mt = 0; mt < 2; ++mt) {
                    #pragma unroll
                    for (int nt = 0; nt < 8; ++nt) {
                        const int nl = nt * 8 + gc;
                        const int n = n0 + wn * 64 + nl;
                        const float2 b2 = *reinterpret_cast<const float2*>(&bias[n]);
                        #pragma unroll
                        for (int rh = 0; rh < 2; ++rh) {
                            const int ml = wm * 32 + mt * 16 + gr + rh * 8;
                            const size_t roff = (size_t)(m0 + ml) * 256 + n;
                            const float2 r2 = *reinterpret_cast<const float2*>(&res[roff]);
                            Cs[nl * 132 + ml]       = c[mt][nt][rh * 2 + 0] + b2.x + r2.x;
                            Cs[(nl + 1) * 132 + ml] = c[mt][nt][rh * 2 + 1] + b2.y + r2.y;
                        }
                    }
                }
            }
            __syncthreads();
            for (int e = tid; e < 2048; e += 256) {
                const int row = e >> 5, q = e & 31;
                *reinterpret_cast<float4*>(
                    &outf[((size_t)(bb * 256 + n0 + nh * 64 + row)) * HW + p0 + q * 4]) =
                    *reinterpret_cast<const float4*>(&Cs[row * 132 + q * 4]);
            }
        }
    }
}

// ===================== input convert (NCHW -> token fp16) ==================
__global__ void __launch_bounds__(256) convert_in(
    const float* __restrict__ x, __half* __restrict__ xh)
{
    __shared__ float sm[64 * 65];
    const int b = blockIdx.z, c0 = blockIdx.y * 64, p0 = blockIdx.x * 64;
    const int tid = threadIdx.x;
    #pragma unroll
    for (int w = 0; w < 16; w++) {
        const int idx = tid + 256 * w;
        const int cl = idx >> 6, pl = idx & 63;
        sm[cl * 65 + pl] = x[((size_t)(b * 256 + c0 + cl)) * HW + p0 + pl];
    }
    __syncthreads();
    #pragma unroll
    for (int w = 0; w < 8; w++) {
        const int idx = tid + 256 * w;
        const int pl = idx >> 5, c2 = (idx & 31) * 2;
        const __half2 v = __halves2half2(
            __float2half_rn(sm[c2 * 65 + pl]),
            __float2half_rn(sm[(c2 + 1) * 65 + pl]));
        *reinterpret_cast<__half2*>(
            &xh[((size_t)(b * HW + p0 + pl)) * 256 + c0 + c2]) = v;
    }
}

// ===================== dw conv 3x3 (sliding window) ========================
__global__ void __launch_bounds__(256) dwconv_kernel(
    const __half* __restrict__ in, __half* __restrict__ oh)
{
    const int by = blockIdx.x;
    const int b = by >> 6, y = by & 63;
    const int tid = threadIdx.x;
    const int c4 = tid & 63;
    const int xq = tid >> 6;

    float w[9][4];
    #pragma unroll
    for (int k = 0; k < 9; k++)
        #pragma unroll
        for (int cc = 0; cc < 4; cc++)
            w[k][cc] = g_dwf[(c4 * 4 + cc) * 9 + k];
    const float4 bs = *reinterpret_cast<const float4*>(&g_dbf[c4 * 4]);

    const __half* pM = in + ((size_t)(b * HW + y * 64)) * 256 + c4 * 4;
    const __half* pU = pM - 64 * 256;
    const __half* pD = pM + 64 * 256;
    const bool hasU = y > 0, hasD = y < 63;

    float L[3][4], M[3][4], R[3][4];

    auto loadcol = [&](int xx, float col[3][4]) {
        uint2 u;
        #pragma unroll
        for (int r = 0; r < 3; r++) {
            const bool ok = (r == 0) ? hasU : ((r == 2) ? hasD : true);
            if (ok) {
                const __half* p = (r == 0) ? pU : ((r == 1) ? pM : pD);
                u = *reinterpret_cast<const uint2*>(p + xx * 256);
                const float2 f01 = __half22float2(*reinterpret_cast<const __half2*>(&u.x));
                const float2 f23 = __half22float2(*reinterpret_cast<const __half2*>(&u.y));
                col[r][0] = f01.x; col[r][1] = f01.y;
                col[r][2] = f23.x; col[r][3] = f23.y;
            } else {
                col[r][0] = col[r][1] = col[r][2] = col[r][3] = 0.f;
            }
        }
    };

    const int x0 = xq * 16;
    if (x0 > 0) loadcol(x0 - 1, L);
    else {
        #pragma unroll
        for (int r = 0; r < 3; r++)
            #pragma unroll
            for (int cc = 0; cc < 4; cc++) L[r][cc] = 0.f;
    }
    loadcol(x0, M);

    #pragma unroll
    for (int xi = 0; xi < 16; ++xi) {
        const int x = x0 + xi;
        if (x < 63) loadcol(x + 1, R);
        else {
            #pragma unroll
            for (int r = 0; r < 3; r++)
                #pragma unroll
                for (int cc = 0; cc < 4; cc++) R[r][cc] = 0.f;
        }
        float a[4] = {bs.x, bs.y, bs.z, bs.w};
        #pragma unroll
        for (int r = 0; r < 3; r++)
            #pragma unroll
            for (int cc = 0; cc < 4; cc++) {
                a[cc] = fmaf(w[r * 3 + 0][cc], L[r][cc], a[cc]);
                a[cc] = fmaf(w[r * 3 + 1][cc], M[r][cc], a[cc]);
                a[cc] = fmaf(w[r * 3 + 2][cc], R[r][cc], a[cc]);
            }
        uint2 uo;
        __half2 t;
        t = __halves2half2(__float2half_rn(a[0]), __float2half_rn(a[1]));
        uo.x = *reinterpret_cast<uint32_t*>(&t);
        t = __halves2half2(__float2half_rn(a[2]), __float2half_rn(a[3]));
        uo.y = *reinterpret_cast<uint32_t*>(&t);
        *reinterpret_cast<uint2*>(
            const_cast<__half*>(oh + ((size_t)(b * HW + y * 64 + x)) * 256 + c4 * 4)) = uo;
        #pragma unroll
        for (int r = 0; r < 3; r++)
            #pragma unroll
            for (int cc = 0; cc < 4; cc++) {
                L[r][cc] = M[r][cc];
                M[r][cc] = R[r][cc];
            }
    }
}

// ===================== LayerNorm + fp16 convert ============================
__global__ void __launch_bounds__(256) ln_split(
    const float* __restrict__ x, __half* __restrict__ oh)
{
    const int warp = threadIdx.x >> 5, lane = threadIdx.x & 31;
    const int tok = blockIdx.x * 8 + warp;
    const float* row = x + (size_t)tok * 256;
    const float4 v0 = *reinterpret_cast<const float4*>(&row[lane * 8]);
    const float4 v1 = *reinterpret_cast<const float4*>(&row[lane * 8 + 4]);
    float s = v0.x + v0.y + v0.z + v0.w + v1.x + v1.y + v1.z + v1.w;
    float s2 = v0.x * v0.x + v0.y * v0.y + v0.z * v0.z + v0.w * v0.w
             + v1.x * v1.x + v1.y * v1.y + v1.z * v1.z + v1.w * v1.w;
    #pragma unroll
    for (int o = 16; o; o >>= 1) {
        s  += __shfl_xor_sync(0xffffffffu, s,  o);
        s2 += __shfl_xor_sync(0xffffffffu, s2, o);
    }
    const float mu = s * (1.f / 256.f);
    const float rs = rsqrtf(s2 * (1.f / 256.f) - mu * mu + EPS);

    float v[8] = {v0.x, v0.y, v0.z, v0.w, v1.x, v1.y, v1.z, v1.w};
    uint4 uh;
    uh.x = packh2((v[0] - mu) * rs, (v[1] - mu) * rs);
    uh.y = packh2((v[2] - mu) * rs, (v[3] - mu) * rs);
    uh.z = packh2((v[4] - mu) * rs, (v[5] - mu) * rs);
    uh.w = packh2((v[6] - mu) * rs, (v[7] - mu) * rs);
    *reinterpret_cast<uint4*>(&oh[(size_t)tok * 256 + lane * 8]) = uh;
}

// ================== window attention on tensor cores =======================
// One block per window; 4 warps, warp = head. Q,K,V fp16; S/O accum fp32.
constexpr int APAD  = 72;                    // halves per smem row
constexpr int APADB = APAD * 2;              // 144 bytes
constexpr int HEAD_SMEM = 2 * 64 * APADB;    // Q plane + K/V plane
constexpr int ATTN_SMEM = 4 * HEAD_SMEM;     // 73728 B

__global__ void __launch_bounds__(128) attn_mma(
    const __half* __restrict__ qkv, __half* __restrict__ oh)
{
    extern __shared__ __align__(128) char asmem[];
    const int win = blockIdx.x;
    const int b = win >> 6, wrem = win & 63;
    const int pbase = b * HW + (wrem >> 3) * 512 + (wrem & 7) * 8;
    const int tid = threadIdx.x;
    const int wid = tid >> 5, lane = tid & 31;
    const int gr = lane >> 2, gc = (lane & 3) << 1;

    const uint32_t qbase = smem_u32(asmem) + wid * HEAD_SMEM;
    const uint32_t kbase = qbase + 64 * APADB;
    __half* Qs = reinterpret_cast<__half*>(asmem) + wid * (HEAD_SMEM / 2);
    __half* Ks = Qs + 64 * APAD;

    const int qo = wid * 64, ko = 256 + wid * 64, vo = 512 + wid * 64;

    // load Q, K [t][d]
    for (int e = lane; e < 512; e += 32) {
        const int t = e >> 3, q = e & 7;
        const int p = pbase + ((t >> 3) << 6) + (t & 7);
        *reinterpret_cast<uint4*>(&Qs[t * APAD + q * 8]) =
            *reinterpret_cast<const uint4*>(&qkv[(size_t)p * 768 + qo + q * 8]);
        *reinterpret_cast<uint4*>(&Ks[t * APAD + q * 8]) =
            *reinterpret_cast<const uint4*>(&qkv[(size_t)p * 768 + ko + q * 8]);
    }
    __syncwarp();

    const uint32_t aoff = (uint32_t)((lane & 15) * APADB + (lane >> 4) * 16);
    const uint32_t boff = (uint32_t)(((lane & 7) + ((lane >> 4) << 3)) * APADB
                                     + ((lane >> 3) & 1) * 16);

    // ---- S = Q K^T ----
    float s[4][8][4];
    #pragma unroll
    for (int i = 0; i < 4; i++)
        #pragma unroll
        for (int j = 0; j < 8; j++)
            #pragma unroll
            for (int r = 0; r < 4; r++) s[i][j][r] = 0.f;

    #pragma unroll
    for (int k16 = 0; k16 < 4; ++k16) {
        const uint32_t kb = k16 * 32;
        uint32_t a[4][4], bf[4][4];
        #pragma unroll
        for (int mt = 0; mt < 4; ++mt)
            ldsm4(qbase + aoff + mt * 16 * APADB + kb, a[mt]);
        #pragma unroll
        for (int np = 0; np < 4; ++np)
            ldsm4(kbase + boff + np * 16 * APADB + kb, bf[np]);
        #pragma unroll
        for (int mt = 0; mt < 4; ++mt)
            #pragma unroll
            for (int nt = 0; nt < 8; ++nt)
                mma16816(s[mt][nt], a[mt],
                         bf[nt >> 1][(nt & 1) * 2], bf[nt >> 1][(nt & 1) * 2 + 1]);
    }

    // ---- softmax (rows spread over quad lanes) ----
    const float sc = 0.125f;
    #pragma unroll
    for (int mt = 0; mt < 4; ++mt) {
        #pragma unroll
        for (int rh = 0; rh < 2; ++rh) {
            float mx = -1e30f;
            #pragma unroll
            for (int nt = 0; nt < 8; ++nt) {
                s[mt][nt][rh * 2]     *= sc;
                s[mt][nt][rh * 2 + 1] *= sc;
                mx = fmaxf(mx, fmaxf(s[mt][nt][rh * 2], s[mt][nt][rh * 2 + 1]));
            }
            mx = fmaxf(mx, __shfl_xor_sync(0xffffffffu, mx, 1));
            mx = fmaxf(mx, __shfl_xor_sync(0xffffffffu, mx, 2));
            float sum = 0.f;
            #pragma unroll
            for (int nt = 0; nt < 8; ++nt) {
                s[mt][nt][rh * 2]     = __expf(s[mt][nt][rh * 2] - mx);
                s[mt][nt][rh * 2 + 1] = __expf(s[mt][nt][rh * 2 + 1] - mx);
                sum += s[mt][nt][rh * 2] + s[mt][nt][rh * 2 + 1];
            }
            sum += __shfl_xor_sync(0xffffffffu, sum, 1);
            sum += __shfl_xor_sync(0xffffffffu, sum, 2);
            const float inv = 1.f / sum;
            #pragma unroll
            for (int nt = 0; nt < 8; ++nt) {
                s[mt][nt][rh * 2]     *= inv;
                s[mt][nt][rh * 2 + 1] *= inv;
            }
        }
    }

    // ---- P fp32 -> fp16 A-fragments (C-frag layout identity) ----
    uint32_t ap[4][4][4];
    #pragma unroll
    for (int mt = 0; mt < 4; ++mt)
        #pragma unroll
        for (int kt = 0; kt < 4; ++kt) {
            ap[mt][kt][0] = packh2(s[mt][2 * kt][0],     s[mt][2 * kt][1]);
            ap[mt][kt][1] = packh2(s[mt][2 * kt][2],     s[mt][2 * kt][3]);
            ap[mt][kt][2] = packh2(s[mt][2 * kt + 1][0], s[mt][2 * kt + 1][1]);
            ap[mt][kt][3] = packh2(s[mt][2 * kt + 1][2], s[mt][2 * kt + 1][3]);
        }

    // ---- load V transposed into K plane: VT[d][t] ----
    __syncwarp();
    for (int e = lane; e < 2048; e += 32) {
        const int t = e >> 5, d2 = (e & 31) * 2;
        const int p = pbase + ((t >> 3) << 6) + (t & 7);
        const __half2 v = *reinterpret_cast<const __half2*>(
            &qkv[(size_t)p * 768 + vo + d2]);
        Ks[d2 * APAD + t] = __low2half(v);
        Ks[(d2 + 1) * APAD + t] = __high2half(v);
    }
    __syncwarp();

    // ---- O = P V ----
    float o[4][8][4];
    #pragma unroll
    for (int i = 0; i < 4; i++)
        #pragma unroll
        for (int j = 0; j < 8; j++)
            #pragma unroll
            for (int r = 0; r < 4; r++) o[i][j][r] = 0.f;

    #pragma unroll
    for (int kt = 0; kt < 4; ++kt) {
        const uint32_t kb = kt * 32;
        uint32_t bf[4][4];
        #pragma unroll
        for (int np = 0; np < 4; ++np)
            ldsm4(kbase + boff + np * 16 * APADB + kb, bf[np]);
        #pragma unroll
        for (int mt = 0; mt < 4; ++mt)
            #pragma unroll
            for (int nt = 0; nt < 8; ++nt)
                mma16816(o[mt][nt], ap[mt][kt],
                         bf[nt >> 1][(nt & 1) * 2], bf[nt >> 1][(nt & 1) * 2 + 1]);
    }

    // ---- write O fp16 token-major [p][256] ----
    #pragma unroll
    for (int mt = 0; mt < 4; ++mt)
        #pragma unroll
        for (int rh = 0; rh < 2; ++rh) {
            const int t = mt * 16 + gr + rh * 8;
            const int p = pbase + ((t >> 3) << 6) + (t & 7);
            #pragma unroll
            for (int nt = 0; nt < 8; ++nt) {
                const int d = nt * 8 + gc;
                *reinterpret_cast<__half2*>(&oh[(size_t)p * 256 + qo + d]) =
                    __halves2half2(__float2half_rn(o[mt][nt][rh * 2]),
                                   __float2half_rn(o[mt][nt][rh * 2 + 1]));
            }
        }
}

// =============================== launcher ==================================
extern "C" void kernel_launch(void* const* d_in, const int* in_sizes, int n_in,
                              void* d_out, int out_size)
{
    (void)in_sizes; (void)n_in; (void)out_size;
    const float* x       = (const float*)d_in[0];
    const float* conv1_w = (const float*)d_in[1];
    const float* conv1_b = (const float*)d_in[2];
    const float* bn1_g   = (const float*)d_in[3];
    const float* bn1_b   = (const float*)d_in[4];
    const float* bn1_m   = (const float*)d_in[5];
    const float* bn1_v   = (const float*)d_in[6];
    const float* dw_w    = (const float*)d_in[7];
    const float* dw_b    = (const float*)d_in[8];
    const float* bn2_g   = (const float*)d_in[9];
    const float* bn2_b   = (const float*)d_in[10];
    const float* bn2_m   = (const float*)d_in[11];
    const float* bn2_v   = (const float*)d_in[12];
    const float* conv3_w = (const float*)d_in[13];
    const float* conv3_b = (const float*)d_in[14];
    const float* ln1_g   = (const float*)d_in[15];
    const float* ln1_b   = (const float*)d_in[16];
    const float* qkv_w   = (const float*)d_in[17];
    const float* qkv_b   = (const float*)d_in[18];
    const float* proj_w  = (const float*)d_in[19];
    const float* proj_b  = (const float*)d_in[20];
    const float* ln2_g   = (const float*)d_in[21];
    const float* ln2_b   = (const float*)d_in[22];
    const float* mlp_w1  = (const float*)d_in[23];
    const float* mlp_b1  = (const float*)d_in[24];
    const float* mlp_w2  = (const float*)d_in[25];
    const float* mlp_b2  = (const float*)d_in[26];
    float* out = (float*)d_out;

    float *x1, *x2, *b1f, *qkvbf, *m1bf;
    __half *xh, *t1h, *t2h, *x1nh, *qkvh, *obh, *x2nh, *hidh;
    __half *w1h, *w3h, *wph, *wqh, *m1h, *w2h;
    cudaGetSymbolAddress((void**)&x1,   g_x1);
    cudaGetSymbolAddress((void**)&x2,   g_x2);
    cudaGetSymbolAddress((void**)&xh,   g_xh);
    cudaGetSymbolAddress((void**)&t1h,  g_t1h);
    cudaGetSymbolAddress((void**)&t2h,  g_t2h);
    cudaGetSymbolAddress((void**)&x1nh, g_x1nh);
    cudaGetSymbolAddress((void**)&qkvh, g_qkvh);
    cudaGetSymbolAddress((void**)&obh,  g_obh);
    cudaGetSymbolAddress((void**)&x2nh, g_x2nh);
    cudaGetSymbolAddress((void**)&hidh, g_hidh);
    cudaGetSymbolAddress((void**)&w1h,  g_w1h);
    cudaGetSymbolAddress((void**)&w3h,  g_w3h);
    cudaGetSymbolAddress((void**)&wph,  g_wph);
    cudaGetSymbolAddress((void**)&wqh,  g_wqh);
    cudaGetSymbolAddress((void**)&m1h,  g_m1h);
    cudaGetSymbolAddress((void**)&w2h,  g_w2h);
    cudaGetSymbolAddress((void**)&b1f,   g_b1f);
    cudaGetSymbolAddress((void**)&qkvbf, g_qkvbf);
    cudaGetSymbolAddress((void**)&m1bf,  g_m1bf);

    cudaFuncSetAttribute(hgemm<256, 0>,
        cudaFuncAttributeMaxDynamicSharedMemorySize, GEMM_SMEM);
    cudaFuncSetAttribute(hgemm<256, 1>,
        cudaFuncAttributeMaxDynamicSharedMemorySize, GEMM_SMEM);
    cudaFuncSetAttribute(hgemm<256, 2>,
        cudaFuncAttributeMaxDynamicSharedMemorySize, GEMM_SMEM);
    cudaFuncSetAttribute(hgemm<256, 3>,
        cudaFuncAttributeMaxDynamicSharedMemorySize, GEMM_SMEM);
    cudaFuncSetAttribute(hgemm<1024, 4>,
        cudaFuncAttributeMaxDynamicSharedMemorySize, GEMM_SMEM);
    cudaFuncSetAttribute(attn_mma,
        cudaFuncAttributeMaxDynamicSharedMemorySize, ATTN_SMEM);

    // 0) fold BN/LN into weights, fp16 convert
    prep_kernel<<<1024, 256>>>(conv1_w, conv1_b, bn1_g, bn1_b, bn1_m, bn1_v,
                               dw_w, dw_b, bn2_g, bn2_b, bn2_m, bn2_v,
                               conv3_w, proj_w, mlp_w2,
                               qkv_w, qkv_b, ln1_g, ln1_b,
                               mlp_w1, mlp_b1, ln2_g, ln2_b);

    // 1) x -> xh fp16 token-major
    convert_in<<<dim3(64, 4, 16), 256>>>(x, xh);
    // 2) conv1 + BN1 -> t1 fp16
    hgemm<256, 0><<<dim3(2, 512), 256, GEMM_SMEM>>>(
        xh, w1h, b1f, nullptr, nullptr, t1h, 256);
    // 3) dw3x3 + BN2 -> t2 fp16
    dwconv_kernel<<<1024, 256>>>(t1h, t2h);
    // 4) conv3 + residual(x NCHW) -> x1 fp32 token-major
    hgemm<256, 3><<<dim3(2, 512), 256, GEMM_SMEM>>>(
        t2h, w3h, conv3_b, x, x1, nullptr, 256);
    // 5) LN1 -> x1n fp16
    ln_split<<<8192, 256>>>(x1, x1nh);
    // 6) QKV -> qkv fp16 [tok][768]
    hgemm<256, 0><<<dim3(6, 512), 256, GEMM_SMEM>>>(
        x1nh, wqh, qkvbf, nullptr, nullptr, qkvh, 768);
    // 7) window attention (tensor cores) -> ob fp16
    attn_mma<<<1024, 128, ATTN_SMEM>>>(qkvh, obh);
    // 8) proj + residual(x1) -> x2 fp32
    hgemm<256, 1><<<dim3(2, 512), 256, GEMM_SMEM>>>(
        obh, wph, proj_b, x1, x2, nullptr, 256);
    // 9) LN2 -> x2n fp16
    ln_split<<<8192, 256>>>(x2, x2nh);
    // 10) MLP1 + GELU -> hid fp16 [tok][1024]
    hgemm<256, 2><<<dim3(8, 512), 256, GEMM_SMEM>>>(
        x2nh, m1h, m1bf, nullptr, nullptr, hidh, 1024);
    // 11) MLP2 + residual(x2) -> out NCHW fp32
    hgemm<1024, 4><<<dim3(2, 512), 256, GEMM_SMEM>>>(
        hidh, w2h, mlp_b2, x2, out, nullptr, 256);
}